// round 12
// baseline (speedup 1.0000x reference)
#include <cuda_runtime.h>
#include <cuda_fp16.h>
#include <stdint.h>
#include <math.h>

// ---- problem constants ----
#define Lx   12
#define Dd   726
#define Hh   16
#define HDd  45
#define Tt   258
#define Vv   50257
#define Bbt  16
#define FFf  2904           // 4*D
#define NT   (Bbt*Tt)       // 4128 tokens
#define HHd  (Hh*HDd)       // 720
#define QKVW (3*HHd)        // 2160

#define PDd  728            // Dd padded to 8
#define PVv  50264          // Vv padded to 8

#define F_BIAS  1
#define F_RELU  2
#define F_RESID 4
#define F_SPLIT 8
#define F_NOLO  16          // skip A-lo plane (single-MMA path)

// ---- fp32 scratch ----
__device__ float g_x   [NT*Dd];
__device__ float g_qkv [NT*QKVW];

// ---- fp16 planes: activations hi+lo, weights hi only ----
__device__ __half g_hh [NT*PDd],  g_hl [NT*PDd];     // LN output
__device__ __half g_oh [NT*HHd],  g_ol [NT*HHd];     // attn output
__device__ __half g_ffh[NT*FFf],  g_ffl[NT*FFf];     // relu(ff1)
__device__ __half g_wqkv[Lx*Dd*QKVW];
__device__ __half g_wp  [Lx*HHd*PDd];
__device__ __half g_w1  [Lx*Dd*FFf];
__device__ __half g_w2  [Lx*FFf*PDd];
__device__ __half g_wlm [Dd*PVv];

// =====================================================================
// helpers
// =====================================================================
__device__ __forceinline__ uint32_t smem_u32(const void* p) {
    uint32_t a;
    asm("{ .reg .u64 t; cvta.to.shared.u64 t, %1; cvt.u32.u64 %0, t; }"
        : "=r"(a) : "l"(p));
    return a;
}
__device__ __forceinline__ void ldsm4(uint32_t& r0, uint32_t& r1,
                                      uint32_t& r2, uint32_t& r3, uint32_t addr) {
    asm volatile("ldmatrix.sync.aligned.m8n8.x4.shared.b16 {%0,%1,%2,%3}, [%4];"
                 : "=r"(r0), "=r"(r1), "=r"(r2), "=r"(r3) : "r"(addr));
}
__device__ __forceinline__ void ldsm4t(uint32_t& r0, uint32_t& r1,
                                       uint32_t& r2, uint32_t& r3, uint32_t addr) {
    asm volatile("ldmatrix.sync.aligned.m8n8.x4.trans.shared.b16 {%0,%1,%2,%3}, [%4];"
                 : "=r"(r0), "=r"(r1), "=r"(r2), "=r"(r3) : "r"(addr));
}
__device__ __forceinline__ void mma16816(float* c, const uint32_t* a,
                                         uint32_t b0, uint32_t b1) {
    asm volatile(
        "mma.sync.aligned.m16n8k16.row.col.f32.f16.f16.f32 "
        "{%0,%1,%2,%3},{%4,%5,%6,%7},{%8,%9},{%0,%1,%2,%3};"
        : "+f"(c[0]), "+f"(c[1]), "+f"(c[2]), "+f"(c[3])
        : "r"(a[0]), "r"(a[1]), "r"(a[2]), "r"(a[3]), "r"(b0), "r"(b1));
}
__device__ __forceinline__ void cpa16(uint32_t dst, const void* src, int bytes) {
    asm volatile("cp.async.cg.shared.global [%0], [%1], 16, %2;"
                 :: "r"(dst), "l"(src), "r"(bytes));
}
__device__ __forceinline__ void cpa_commit() {
    asm volatile("cp.async.commit_group;" ::: "memory");
}
__device__ __forceinline__ void cpa_wait0() {
    asm volatile("cp.async.wait_group 0;" ::: "memory");
}
__device__ __forceinline__ void split2h(float v, __half& h, __half& l) {
    h = __float2half_rn(v);
    l = __float2half_rn(v - __half2float(h));
}

// =====================================================================
// GEMM: C[M,N] = A[M,K] @ B[K,N]; A = hi(+lo) fp16 planes, B = fp16.
// CTA 128x128, K-chunk 64, 2-stage double buffer, one sync per chunk.
// Inner loop: ALL ldmatrix of a ks-step batched before the MMA burst.
// =====================================================================
#define KCH 64
#define STG 49152
#define HG_SMEM (2*STG)     // 98304

__global__ __launch_bounds__(256, 2) void hgemm_k(
    const __half* __restrict__ Ah, const __half* __restrict__ Al,
    const __half* __restrict__ Bh,
    const float* __restrict__ bias, const float* __restrict__ resid,
    float* __restrict__ C, __half* __restrict__ Ch, __half* __restrict__ Cl,
    int M, int N, int K, int ApK, int BpN, int ldc, int flags)
{
    extern __shared__ __align__(1024) char smraw[];
    const uint32_t sbase = smem_u32(smraw);

    const int tid  = threadIdx.x;
    const int wid  = tid >> 5;
    const int lane = tid & 31;
    const int warp_m = wid & 3;
    const int warp_n = wid >> 2;

    const int m0 = blockIdx.x << 7;
    const int n0 = blockIdx.y << 7;
    const int nCh = (K + KCH - 1) / KCH;
    const bool uselo = !(flags & F_NOLO);

    float c[2][8][4];
    #pragma unroll
    for (int i = 0; i < 2; i++)
        #pragma unroll
        for (int j = 0; j < 8; j++)
            #pragma unroll
            for (int q = 0; q < 4; q++) c[i][j][q] = 0.f;

    // A: unswizzled base + per-row mask; XOR applied AFTER the ks add.
    uint32_t abase[2], amask[2];
    #pragma unroll
    for (int mt = 0; mt < 2; mt++) {
        uint32_t o = (uint32_t)((warp_m * 32 + mt * 16 + (lane & 15)) * 128
                                + ((lane >> 4) << 4));
        abase[mt] = o;
        amask[mt] = (o >> 3) & 0x70u;
    }
    // B: ks step (+4096) is above mask bits -> swizzle-additive
    uint32_t boff[4];
    #pragma unroll
    for (int nt2 = 0; nt2 < 4; nt2++) {
        uint32_t o = (uint32_t)((((lane >> 3) & 1) * 8 + (lane & 7)) * 256
                                + warp_n * 128 + nt2 * 32 + ((lane >> 4) << 4));
        boff[nt2] = o ^ ((o >> 4) & 0xF0u);
    }

    auto issue = [&](int ch) {
        const uint32_t st = sbase + (uint32_t)(ch & 1) * STG;
        const int k0 = ch * KCH;
        // A hi(+lo): 128 rows x 8 segs of 16B
        #pragma unroll
        for (int i = 0; i < 4; i++) {
            int g = tid + (i << 8);
            int seg = g & 7, r = g >> 3;
            int m = m0 + r, k = k0 + (seg << 3);
            int bytes = (m < M && k < ApK) ? 16 : 0;
            size_t gi = (size_t)m * ApK + k;
            uint32_t o = (uint32_t)(r * 128 + (seg << 4));
            o ^= (o >> 3) & 0x70u;
            cpa16(st + o, bytes ? (const void*)(Ah + gi) : (const void*)Ah, bytes);
            if (uselo)
                cpa16(st + 16384u + o, bytes ? (const void*)(Al + gi) : (const void*)Al, bytes);
        }
        // B: 64 rows x 16 segs of 16B
        #pragma unroll
        for (int i = 0; i < 4; i++) {
            int g = tid + (i << 8);
            int seg = g & 15, r = g >> 4;
            int k = k0 + r, n = n0 + (seg << 3);
            int bytes = (k < K && n < BpN) ? 16 : 0;
            const void* p = bytes ? (const void*)(Bh + (size_t)k * BpN + n)
                                  : (const void*)Bh;
            uint32_t o = (uint32_t)(r * 256 + (seg << 4));
            o ^= (o >> 4) & 0xF0u;
            cpa16(st + 32768u + o, p, bytes);
        }
    };

    issue(0);
    cpa_commit();

    for (int ch = 0; ch < nCh; ch++) {
        cpa_wait0();
        __syncthreads();

        if (ch + 1 < nCh) {
            issue(ch + 1);
            cpa_commit();
        }

        const uint32_t st = sbase + (uint32_t)(ch & 1) * STG;
        #pragma unroll
        for (int ks = 0; ks < 4; ks++) {
            // ---- batch ALL fragment loads for this ks ----
            uint32_t ahi[2][4], alo[2][4], bh[4][4];
            #pragma unroll
            for (int mt = 0; mt < 2; mt++) {
                uint32_t ad = st + ((abase[mt] + (uint32_t)(ks * 32)) ^ amask[mt]);
                ldsm4(ahi[mt][0], ahi[mt][1], ahi[mt][2], ahi[mt][3], ad);
            }
            if (uselo) {
                #pragma unroll
                for (int mt = 0; mt < 2; mt++) {
                    uint32_t ad = st + ((abase[mt] + (uint32_t)(ks * 32)) ^ amask[mt]);
                    ldsm4(alo[mt][0], alo[mt][1], alo[mt][2], alo[mt][3], ad + 16384u);
                }
            }
            #pragma unroll
            for (int nt2 = 0; nt2 < 4; nt2++)
                ldsm4t(bh[nt2][0], bh[nt2][1], bh[nt2][2], bh[nt2][3],
                       st + 32768u + boff[nt2] + (uint32_t)(ks * 4096));

            // ---- MMA burst (all operands resident) ----
            #pragma unroll
            for (int nt2 = 0; nt2 < 4; nt2++) {
                #pragma unroll
                for (int hh = 0; hh < 2; hh++) {
                    const int nt = nt2 * 2 + hh;
                    #pragma unroll
                    for (int mt = 0; mt < 2; mt++) {
                        mma16816(c[mt][nt], ahi[mt], bh[nt2][hh * 2], bh[nt2][hh * 2 + 1]);
                        if (uselo)
                            mma16816(c[mt][nt], alo[mt], bh[nt2][hh * 2], bh[nt2][hh * 2 + 1]);
                    }
                }
            }
        }
    }

    // ---- epilogue ----
    #pragma unroll
    for (int mt = 0; mt < 2; mt++) {
        #pragma unroll
        for (int nt = 0; nt < 8; nt++) {
            int rb = m0 + warp_m * 32 + mt * 16 + (lane >> 2);
            int nc = n0 + warp_n * 64 + nt * 8 + ((lane & 3) << 1);
            #pragma unroll
            for (int half = 0; half < 2; half++) {
                int m = rb + half * 8;
                if (m < M) {
                    #pragma unroll
                    for (int j = 0; j < 2; j++) {
                        int n = nc + j;
                        if (n < N) {
                            float v = c[mt][nt][half * 2 + j];
                            if (flags & F_BIAS)  v += bias[n];
                            if (flags & F_RESID) v += resid[(size_t)m * ldc + n];
                            if (flags & F_RELU)  v = fmaxf(v, 0.f);
                            if (flags & F_SPLIT) {
                                __half h, l;
                                split2h(v, h, l);
                                Ch[(size_t)m * ldc + n] = h;
                                Cl[(size_t)m * ldc + n] = l;
                            } else {
                                C[(size_t)m * ldc + n] = v;
                            }
                        }
                    }
                }
            }
        }
    }
}

// =====================================================================
// weight prep kernels
// =====================================================================
__global__ void repack_qkv_k(const float* __restrict__ Wq,
                             const float* __restrict__ Wk,
                             const float* __restrict__ Wv,
                             __half* __restrict__ d) {
    int i = blockIdx.x * blockDim.x + threadIdx.x;
    const int total = Lx * Dd * QKVW;
    if (i >= total) return;
    int j    = i % QKVW;
    int rest = i / QKVW;
    int dd   = rest % Dd;
    int l    = rest / Dd;
    int sel = j / HHd;
    int n   = j % HHd;
    int h  = n / HDd;
    int kk = n % HDd;
    const float* src = (sel == 0) ? Wq : (sel == 1) ? Wk : Wv;
    d[i] = __float2half_rn(src[((l * Hh + h) * Dd + dd) * HDd + kk]);
}

// vectorized: one half2 per thread
__global__ void tohalf_pad_k(const float* __restrict__ src,
                             __half2* __restrict__ d,
                             int R, int C, int Cp2) {   // Cp2 = Cp/2
    int i = blockIdx.x * blockDim.x + threadIdx.x;
    if (i >= R * Cp2) return;
    int r = i / Cp2, c2 = (i - r * Cp2) << 1;
    const float* row = src + (size_t)r * C;
    float v0 = (c2     < C) ? row[c2]     : 0.f;
    float v1 = (c2 + 1 < C) ? row[c2 + 1] : 0.f;
    d[i] = __floats2half2_rn(v0, v1);
}

// ---- embedding ----
__global__ void embed_k(const int* __restrict__ idx,
                        const float* __restrict__ tok,
                        const float* __restrict__ pos) {
    int i = blockIdx.x * blockDim.x + threadIdx.x;
    if (i >= NT * Dd) return;
    int d = i % Dd;
    int n = i / Dd;
    int t = n % Tt;
    g_x[i] = tok[idx[n] * Dd + d] + pos[t * Dd + d];
}

// ---- layernorm -> hi/lo planes ----
__global__ void lnorm_split_k(const float* __restrict__ in,
                              __half* __restrict__ oh,
                              __half* __restrict__ ol,
                              const float* __restrict__ g, const float* __restrict__ b) {
    int row = blockIdx.x;
    const float* xr = in + (size_t)row * Dd;
    __shared__ float r1[256];
    __shared__ float r2[256];
    float s = 0.f, ss = 0.f;
    for (int d = threadIdx.x; d < Dd; d += 256) {
        float v = xr[d];
        s += v; ss += v * v;
    }
    r1[threadIdx.x] = s; r2[threadIdx.x] = ss;
    __syncthreads();
    for (int o = 128; o > 0; o >>= 1) {
        if (threadIdx.x < o) { r1[threadIdx.x] += r1[threadIdx.x + o]; r2[threadIdx.x] += r2[threadIdx.x + o]; }
        __syncthreads();
    }
    float mean = r1[0] / Dd;
    float var  = r2[0] / Dd - mean * mean;
    float inv  = rsqrtf(var + 1e-5f);
    for (int d = threadIdx.x; d < PDd; d += 256) {
        float v = 0.f;
        if (d < Dd) v = (xr[d] - mean) * inv * g[d] + b[d];
        __half hi, lo;
        split2h(v, hi, lo);
        oh[(size_t)row * PDd + d] = hi;
        ol[(size_t)row * PDd + d] = lo;
    }
}

// =====================================================================
// attention (K,V staged in smem once per (b,h))
// =====================================================================
#define KSTR 47
#define VSTR 288
#define ATT_SMEM ((Tt*KSTR + HDd*VSTR + 8*48 + 8*46) * 4)

__global__ __launch_bounds__(256, 2) void attn_k(const float* __restrict__ qkv,
                                                 __half* __restrict__ oh,
                                                 __half* __restrict__ ol) {
    extern __shared__ float smf[];
    float* Ksm = smf;
    float* Vt  = Ksm + Tt * KSTR;
    float* qsm = Vt + HDd * VSTR;
    float* osm = qsm + 8 * 48;

    const int h = blockIdx.x, b = blockIdx.y;
    const int tid = threadIdx.x, w = tid >> 5, lane = tid & 31;
    const float* base = qkv + (size_t)(b * Tt) * QKVW + h * HDd;

    for (int idx = tid; idx < Tt * HDd; idx += 256) {
        int s = idx / HDd, d = idx - s * HDd;
        const float* row = base + (size_t)s * QKVW;
        Ksm[s * KSTR + d] = row[HHd + d];
        Vt [d * VSTR + s] = row[2 * HHd + d];
    }
    for (int idx = tid; idx < HDd * (VSTR - Tt); idx += 256) {
        int d = idx / (VSTR - Tt), s = Tt + idx % (VSTR - Tt);
        Vt[d * VSTR + s] = 0.f;
    }
    __syncthreads();

    const float scale = rsqrtf((float)HDd);
    for (int t = w; t < Tt; t += 8) {
        for (int d = lane; d < HDd; d += 32)
            qsm[w * 48 + d] = base[(size_t)t * QKVW + d];
        __syncwarp();

        const int ngrp = (t >> 5) + 1;
        float p[9];
        float m = -1e30f;
        for (int i = 0; i < ngrp; i++) {
            int s = lane + (i << 5);
            float acc = -1e30f;
            if (s <= t) {
                float a = 0.f;
                #pragma unroll
                for (int d = 0; d < HDd; d++)
                    a += qsm[w * 48 + d] * Ksm[s * KSTR + d];
                acc = a * scale;
            }
            p[i] = acc;
            m = fmaxf(m, acc);
        }
        #pragma unroll
        for (int o = 16; o; o >>= 1) m = fmaxf(m, __shfl_xor_sync(0xFFFFFFFFu, m, o));

        float sum = 0.f;
        for (int i = 0; i < ngrp; i++) {
            float e = __expf(p[i] - m);
            p[i] = e; sum += e;
        }
        #pragma unroll
        for (int o = 16; o; o >>= 1) sum += __shfl_xor_sync(0xFFFFFFFFu, sum, o);
        const float inv = 1.f / sum;

        for (int d = 0; d < HDd; d++) {
            float part = 0.f;
            for (int i = 0; i < ngrp; i++)
                part += p[i] * Vt[d * VSTR + lane + (i << 5)];
            #pragma unroll
            for (int o = 16; o; o >>= 1) part += __shfl_xor_sync(0xFFFFFFFFu, part, o);
            if (lane == 0) osm[w * 46 + d] = part * inv;
        }
        __syncwarp();

        for (int d = lane; d < HDd; d += 32) {
            float v = osm[w * 46 + d];
            __half hi, lo;
            split2h(v, hi, lo);
            oh[(size_t)(b * Tt + t) * HHd + h * HDd + d] = hi;
            ol[(size_t)(b * Tt + t) * HHd + h * HDd + d] = lo;
        }
        __syncwarp();
    }
}

// ---- host ----
template <typename T>
static T* sym_addr(const void* sym) {
    void* p = nullptr;
    cudaGetSymbolAddress(&p, sym);
    return (T*)p;
}

static void tgemm(const __half* Ah, const __half* Al, const __half* Bh,
                  const float* bias, const float* resid,
                  float* C, __half* Ch, __half* Cl,
                  int M, int N, int K, int ApK, int BpN, int ldc, int flags) {
    dim3 g((M + 127) / 128, (N + 127) / 128);
    hgemm_k<<<g, 256, HG_SMEM>>>(Ah, Al, Bh, bias, resid, C, Ch, Cl,
                                 M, N, K, ApK, BpN, ldc, flags);
}

extern "C" void kernel_launch(void* const* d_in, const int* in_sizes, int n_in,
                              void* d_out, int out_size) {
    const int*   idx     = (const int*)  d_in[0];
    const float* tok_emb = (const float*)d_in[1];
    const float* pos_emb = (const float*)d_in[2];
    const float* Wq      = (const float*)d_in[3];
    const float* Wk      = (const float*)d_in[4];
    const float* Wv      = (const float*)d_in[5];
    const float* Wproj   = (const float*)d_in[6];
    const float* bproj   = (const float*)d_in[7];
    const float* ln1_g   = (const float*)d_in[8];
    const float* ln1_b   = (const float*)d_in[9];
    const float* ln2_g   = (const float*)d_in[10];
    const float* ln2_b   = (const float*)d_in[11];
    const float* W1      = (const float*)d_in[12];
    const float* b1      = (const float*)d_in[13];
    const float* W2      = (const float*)d_in[14];
    const float* b2      = (const float*)d_in[15];
    const float* lnf_g   = (const float*)d_in[16];
    const float* lnf_b   = (const float*)d_in[17];
    const float* Wlm     = (const float*)d_in[18];
    const float* blm     = (const float*)d_in[19];
    float* out = (float*)d_out;

    static bool attr_set = false;
    if (!attr_set) {
        cudaFuncSetAttribute(hgemm_k, cudaFuncAttributeMaxDynamicSharedMemorySize, HG_SMEM);
        cudaFuncSetAttribute(attn_k,  cudaFuncAttributeMaxDynamicSharedMemorySize, ATT_SMEM);
        attr_set = true;
    }

    float* px   = sym_addr<float>(g_x);
    float* pqkv = sym_addr<float>(g_qkv);
    __half* phh  = sym_addr<__half>(g_hh);
    __half* phl  = sym_addr<__half>(g_hl);
    __half* poh  = sym_addr<__half>(g_oh);
    __half* pol  = sym_addr<__half>(g_ol);
    __half* pffh = sym_addr<__half>(g_ffh);
    __half* pffl = sym_addr<__half>(g_ffl);
    __half* pwq  = sym_addr<__half>(g_wqkv);
    __half* pwp  = sym_addr<__half>(g_wp);
    __half* pw1  = sym_addr<__half>(g_w1);
    __half* pw2  = sym_addr<__half>(g_w2);
    __half* pwlm = sym_addr<__half>(g_wlm);

    // ---- weight prep ----
    {
        int tot = Lx * Dd * QKVW;
        repack_qkv_k<<<(tot + 255) / 256, 256>>>(Wq, Wk, Wv, pwq);
        tot = Lx * HHd * PDd / 2;
        tohalf_pad_k<<<(tot + 255) / 256, 256>>>(Wproj, (__half2*)pwp, Lx * HHd, Dd, PDd / 2);
        tot = Lx * Dd * FFf / 2;
        tohalf_pad_k<<<(tot + 255) / 256, 256>>>(W1, (__half2*)pw1, Lx * Dd, FFf, FFf / 2);
        tot = Lx * FFf * PDd / 2;
        tohalf_pad_k<<<(tot + 255) / 256, 256>>>(W2, (__half2*)pw2, Lx * FFf, Dd, PDd / 2);
        tot = Dd * PVv / 2;
        tohalf_pad_k<<<(tot + 255) / 256, 256>>>(Wlm, (__half2*)pwlm, Dd, Vv, PVv / 2);
    }
    {
        const int total = NT * Dd;
        embed_k<<<(total + 255) / 256, 256>>>(idx, tok_emb, pos_emb);
    }

    dim3 gATT(Hh, Bbt);

    for (int l = 0; l < Lx; l++) {
        lnorm_split_k<<<NT, 256>>>(px, phh, phl, ln1_g + l * Dd, ln1_b + l * Dd);
        tgemm(phh, phl, pwq + (size_t)l * Dd * QKVW,
              nullptr, nullptr, pqkv, nullptr, nullptr,
              NT, QKVW, Dd, PDd, QKVW, QKVW, 0);
        attn_k<<<gATT, 256, ATT_SMEM>>>(pqkv, poh, pol);
        tgemm(poh, pol, pwp + (size_t)l * HHd * PDd,
              bproj + l * Dd, px, px, nullptr, nullptr,
              NT, Dd, HHd, HHd, PDd, Dd, F_BIAS | F_RESID);
        lnorm_split_k<<<NT, 256>>>(px, phh, phl, ln2_g + l * Dd, ln2_b + l * Dd);
        tgemm(phh, phl, pw1 + (size_t)l * Dd * FFf,
              b1 + (size_t)l * FFf, nullptr, nullptr, pffh, pffl,
              NT, FFf, Dd, PDd, FFf, FFf, F_BIAS | F_RELU | F_SPLIT);
        tgemm(pffh, pffl, pw2 + (size_t)l * FFf * PDd,
              b2 + l * Dd, px, px, nullptr, nullptr,
              NT, Dd, FFf, FFf, PDd, Dd, F_BIAS | F_RESID);
    }

    lnorm_split_k<<<NT, 256>>>(px, phh, phl, lnf_g, lnf_b);
    // LM head: single-plane A
    tgemm(phh, phl, pwlm, blm, nullptr, out, nullptr, nullptr,
          NT, Vv, Dd, PDd, PVv, Vv, F_BIAS | F_NOLO);
}

// round 14
// speedup vs baseline: 1.0371x; 1.0371x over previous
#include <cuda_runtime.h>
#include <cuda_fp16.h>
#include <stdint.h>
#include <math.h>

// ---- problem constants ----
#define Lx   12
#define Dd   726
#define Hh   16
#define HDd  45
#define Tt   258
#define Vv   50257
#define Bbt  16
#define FFf  2904           // 4*D
#define NT   (Bbt*Tt)       // 4128 tokens
#define HHd  (Hh*HDd)       // 720
#define QKVW (3*HHd)        // 2160

#define PDd  728            // Dd padded to 8
#define PVv  50264          // Vv padded to 8

#define F_BIAS  1
#define F_RELU  2
#define F_RESID 4
#define F_SPLIT 8
#define F_NOLO  16          // skip A-lo plane (single-MMA path)

// ---- fp32 scratch ----
__device__ float g_x   [NT*Dd];
__device__ float g_qkv [NT*QKVW];

// ---- fp16 planes: activations hi+lo, weights hi only ----
__device__ __half g_hh [NT*PDd],  g_hl [NT*PDd];     // LN output
__device__ __half g_oh [NT*HHd],  g_ol [NT*HHd];     // attn output
__device__ __half g_ffh[NT*FFf],  g_ffl[NT*FFf];     // relu(ff1)
__device__ __half g_wqkv[Lx*Dd*QKVW];
__device__ __half g_wp  [Lx*HHd*PDd];
__device__ __half g_w1  [Lx*Dd*FFf];
__device__ __half g_w2  [Lx*FFf*PDd];
__device__ __half g_wlm [Dd*PVv];

// =====================================================================
// helpers
// =====================================================================
__device__ __forceinline__ uint32_t smem_u32(const void* p) {
    uint32_t a;
    asm("{ .reg .u64 t; cvta.to.shared.u64 t, %1; cvt.u32.u64 %0, t; }"
        : "=r"(a) : "l"(p));
    return a;
}
__device__ __forceinline__ void ldsm4(uint32_t& r0, uint32_t& r1,
                                      uint32_t& r2, uint32_t& r3, uint32_t addr) {
    asm volatile("ldmatrix.sync.aligned.m8n8.x4.shared.b16 {%0,%1,%2,%3}, [%4];"
                 : "=r"(r0), "=r"(r1), "=r"(r2), "=r"(r3) : "r"(addr));
}
__device__ __forceinline__ void ldsm4t(uint32_t& r0, uint32_t& r1,
                                       uint32_t& r2, uint32_t& r3, uint32_t addr) {
    asm volatile("ldmatrix.sync.aligned.m8n8.x4.trans.shared.b16 {%0,%1,%2,%3}, [%4];"
                 : "=r"(r0), "=r"(r1), "=r"(r2), "=r"(r3) : "r"(addr));
}
__device__ __forceinline__ void mma16816(float* c, const uint32_t* a,
                                         uint32_t b0, uint32_t b1) {
    asm volatile(
        "mma.sync.aligned.m16n8k16.row.col.f32.f16.f16.f32 "
        "{%0,%1,%2,%3},{%4,%5,%6,%7},{%8,%9},{%0,%1,%2,%3};"
        : "+f"(c[0]), "+f"(c[1]), "+f"(c[2]), "+f"(c[3])
        : "r"(a[0]), "r"(a[1]), "r"(a[2]), "r"(a[3]), "r"(b0), "r"(b1));
}
__device__ __forceinline__ void cpa16(uint32_t dst, const void* src, int bytes) {
    asm volatile("cp.async.cg.shared.global [%0], [%1], 16, %2;"
                 :: "r"(dst), "l"(src), "r"(bytes));
}
__device__ __forceinline__ void cpa_commit() {
    asm volatile("cp.async.commit_group;" ::: "memory");
}
__device__ __forceinline__ void cpa_wait0() {
    asm volatile("cp.async.wait_group 0;" ::: "memory");
}
__device__ __forceinline__ void split2h(float v, __half& h, __half& l) {
    h = __float2half_rn(v);
    l = __float2half_rn(v - __half2float(h));
}

// =====================================================================
// GEMM template: C[M,N] = A[M,K] @ B[K,N]; A hi(+lo) fp16, B fp16.
// CTA tile 128 x BN (BN in {128,64}); K-chunk 64; 2-stage double buffer.
// 8 warps: 4m x 2n; warp tile 32 x (BN/2).
// Stage: Ahi 16KB | Alo 16KB | B (KCH*BN*2)
// =====================================================================
#define KCH 64

template<int BN>
__global__ __launch_bounds__(256, 2) void hgemm_k(
    const __half* __restrict__ Ah, const __half* __restrict__ Al,
    const __half* __restrict__ Bh,
    const float* __restrict__ bias, const float* __restrict__ resid,
    float* __restrict__ C, __half* __restrict__ Ch, __half* __restrict__ Cl,
    int M, int N, int K, int ApK, int BpN, int ldc, int flags)
{
    constexpr int NT2   = BN / 32;                 // 16-col B groups per warp
    constexpr int BRB   = BN * 2;                  // B row bytes (256 / 128)
    constexpr uint32_t SB   = 32768;               // B plane offset in stage
    constexpr uint32_t STGT = SB + (uint32_t)(KCH * BN * 2);

    extern __shared__ __align__(1024) char smraw[];
    const uint32_t sbase = smem_u32(smraw);

    const int tid  = threadIdx.x;
    const int wid  = tid >> 5;
    const int lane = tid & 31;
    const int warp_m = wid & 3;
    const int warp_n = wid >> 2;

    const int m0 = blockIdx.x << 7;
    const int n0 = blockIdx.y * BN;
    const int nCh = (K + KCH - 1) / KCH;
    const bool uselo = !(flags & F_NOLO);

    float c[2][2 * NT2][4];
    #pragma unroll
    for (int i = 0; i < 2; i++)
        #pragma unroll
        for (int j = 0; j < 2 * NT2; j++)
            #pragma unroll
            for (int q = 0; q < 4; q++) c[i][j][q] = 0.f;

    // A: unswizzled base + per-row mask; XOR applied AFTER the ks add.
    uint32_t abase[2], amask[2];
    #pragma unroll
    for (int mt = 0; mt < 2; mt++) {
        uint32_t o = (uint32_t)((warp_m * 32 + mt * 16 + (lane & 15)) * 128
                                + ((lane >> 4) << 4));
        abase[mt] = o;
        amask[mt] = (o >> 3) & 0x70u;
    }
    // B fragment offsets in BYTES (warp covers BN/2 cols = BN bytes).
    // Swizzled at precompute; ks step is above mask source bits -> additive.
    uint32_t boff[NT2];
    #pragma unroll
    for (int nt2 = 0; nt2 < NT2; nt2++) {
        uint32_t o = (uint32_t)((((lane >> 3) & 1) * 8 + (lane & 7)) * BRB
                                + warp_n * BN + nt2 * 32 + ((lane >> 4) << 4));
        if (BN == 128) o ^= (o >> 4) & 0xF0u;
        else           o ^= (o >> 3) & 0x70u;
        boff[nt2] = o;
    }

    auto issue = [&](int ch) {
        const uint32_t st = sbase + (uint32_t)(ch & 1) * STGT;
        const int k0 = ch * KCH;
        // A hi(+lo): 128 rows x 8 segs of 16B
        #pragma unroll
        for (int i = 0; i < 4; i++) {
            int g = tid + (i << 8);
            int seg = g & 7, r = g >> 3;
            int m = m0 + r, k = k0 + (seg << 3);
            int bytes = (m < M && k < ApK) ? 16 : 0;
            size_t gi = (size_t)m * ApK + k;
            uint32_t o = (uint32_t)(r * 128 + (seg << 4));
            o ^= (o >> 3) & 0x70u;
            cpa16(st + o, bytes ? (const void*)(Ah + gi) : (const void*)Ah, bytes);
            if (uselo)
                cpa16(st + 16384u + o, bytes ? (const void*)(Al + gi) : (const void*)Al, bytes);
        }
        // B: KCH rows x (BN/8) segs of 16B
        #pragma unroll
        for (int i = 0; i < (KCH * BN / 8) / 256; i++) {
            int g = tid + (i << 8);
            int seg = g & (BN / 8 - 1);
            int r   = g / (BN / 8);
            int k = k0 + r, n = n0 + (seg << 3);
            int bytes = (k < K && n < BpN) ? 16 : 0;
            const void* p = bytes ? (const void*)(Bh + (size_t)k * BpN + n)
                                  : (const void*)Bh;
            uint32_t o = (uint32_t)(r * BRB + (seg << 4));
            if (BN == 128) o ^= (o >> 4) & 0xF0u;
            else           o ^= (o >> 3) & 0x70u;
            cpa16(st + SB + o, p, bytes);
        }
    };

    issue(0);
    cpa_commit();

    for (int ch = 0; ch < nCh; ch++) {
        cpa_wait0();
        __syncthreads();

        if (ch + 1 < nCh) {
            issue(ch + 1);
            cpa_commit();
        }

        const uint32_t st = sbase + (uint32_t)(ch & 1) * STGT;
        #pragma unroll
        for (int ks = 0; ks < 4; ks++) {
            uint32_t ahi[2][4], alo[2][4];
            #pragma unroll
            for (int mt = 0; mt < 2; mt++) {
                uint32_t ad = st + ((abase[mt] + (uint32_t)(ks * 32)) ^ amask[mt]);
                ldsm4(ahi[mt][0], ahi[mt][1], ahi[mt][2], ahi[mt][3], ad);
                if (uselo)
                    ldsm4(alo[mt][0], alo[mt][1], alo[mt][2], alo[mt][3], ad + 16384u);
            }
            #pragma unroll
            for (int nt2 = 0; nt2 < NT2; nt2++) {
                uint32_t bh[4];
                ldsm4t(bh[0], bh[1], bh[2], bh[3],
                       st + SB + boff[nt2] + (uint32_t)(ks * 16 * BRB));
                #pragma unroll
                for (int hh = 0; hh < 2; hh++) {
                    const int nt = nt2 * 2 + hh;
                    #pragma unroll
                    for (int mt = 0; mt < 2; mt++) {
                        mma16816(c[mt][nt], ahi[mt], bh[hh * 2], bh[hh * 2 + 1]);
                        if (uselo)
                            mma16816(c[mt][nt], alo[mt], bh[hh * 2], bh[hh * 2 + 1]);
                    }
                }
            }
        }
    }

    // ---- epilogue ----
    #pragma unroll
    for (int mt = 0; mt < 2; mt++) {
        #pragma unroll
        for (int nt = 0; nt < 2 * NT2; nt++) {
            int rb = m0 + warp_m * 32 + mt * 16 + (lane >> 2);
            int nc = n0 + warp_n * (BN / 2) + nt * 8 + ((lane & 3) << 1);
            #pragma unroll
            for (int half = 0; half < 2; half++) {
                int m = rb + half * 8;
                if (m < M) {
                    #pragma unroll
                    for (int j = 0; j < 2; j++) {
                        int n = nc + j;
                        if (n < N) {
                            float v = c[mt][nt][half * 2 + j];
                            if (flags & F_BIAS)  v += bias[n];
                            if (flags & F_RESID) v += resid[(size_t)m * ldc + n];
                            if (flags & F_RELU)  v = fmaxf(v, 0.f);
                            if (flags & F_SPLIT) {
                                __half h, l;
                                split2h(v, h, l);
                                Ch[(size_t)m * ldc + n] = h;
                                Cl[(size_t)m * ldc + n] = l;
                            } else {
                                C[(size_t)m * ldc + n] = v;
                            }
                        }
                    }
                }
            }
        }
    }
}

#define HG_SMEM128 (2 * (32768 + KCH * 128 * 2))   // 98304
#define HG_SMEM64  (2 * (32768 + KCH * 64 * 2))    // 81920

// =====================================================================
// weight prep kernels
// =====================================================================
__global__ void repack_qkv_k(const float* __restrict__ Wq,
                             const float* __restrict__ Wk,
                             const float* __restrict__ Wv,
                             __half* __restrict__ d) {
    int i = blockIdx.x * blockDim.x + threadIdx.x;
    const int total = Lx * Dd * QKVW;
    if (i >= total) return;
    int j    = i % QKVW;
    int rest = i / QKVW;
    int dd   = rest % Dd;
    int l    = rest / Dd;
    int sel = j / HHd;
    int n   = j % HHd;
    int h  = n / HDd;
    int kk = n % HDd;
    const float* src = (sel == 0) ? Wq : (sel == 1) ? Wk : Wv;
    d[i] = __float2half_rn(src[((l * Hh + h) * Dd + dd) * HDd + kk]);
}

__global__ void tohalf_pad_k(const float* __restrict__ src,
                             __half2* __restrict__ d,
                             int R, int C, int Cp2) {
    int i = blockIdx.x * blockDim.x + threadIdx.x;
    if (i >= R * Cp2) return;
    int r = i / Cp2, c2 = (i - r * Cp2) << 1;
    const float* row = src + (size_t)r * C;
    float v0 = (c2     < C) ? row[c2]     : 0.f;
    float v1 = (c2 + 1 < C) ? row[c2 + 1] : 0.f;
    d[i] = __floats2half2_rn(v0, v1);
}

// ---- embedding ----
__global__ void embed_k(const int* __restrict__ idx,
                        const float* __restrict__ tok,
                        const float* __restrict__ pos) {
    int i = blockIdx.x * blockDim.x + threadIdx.x;
    if (i >= NT * Dd) return;
    int d = i % Dd;
    int n = i / Dd;
    int t = n % Tt;
    g_x[i] = tok[idx[n] * Dd + d] + pos[t * Dd + d];
}

// ---- layernorm -> hi/lo planes ----
__global__ void lnorm_split_k(const float* __restrict__ in,
                              __half* __restrict__ oh,
                              __half* __restrict__ ol,
                              const float* __restrict__ g, const float* __restrict__ b) {
    int row = blockIdx.x;
    const float* xr = in + (size_t)row * Dd;
    __shared__ float r1[256];
    __shared__ float r2[256];
    float s = 0.f, ss = 0.f;
    for (int d = threadIdx.x; d < Dd; d += 256) {
        float v = xr[d];
        s += v; ss += v * v;
    }
    r1[threadIdx.x] = s; r2[threadIdx.x] = ss;
    __syncthreads();
    for (int o = 128; o > 0; o >>= 1) {
        if (threadIdx.x < o) { r1[threadIdx.x] += r1[threadIdx.x + o]; r2[threadIdx.x] += r2[threadIdx.x + o]; }
        __syncthreads();
    }
    float mean = r1[0] / Dd;
    float var  = r2[0] / Dd - mean * mean;
    float inv  = rsqrtf(var + 1e-5f);
    for (int d = threadIdx.x; d < PDd; d += 256) {
        float v = 0.f;
        if (d < Dd) v = (xr[d] - mean) * inv * g[d] + b[d];
        __half hi, lo;
        split2h(v, hi, lo);
        oh[(size_t)row * PDd + d] = hi;
        ol[(size_t)row * PDd + d] = lo;
    }
}

// =====================================================================
// attention (K,V staged in smem once per (b,h))
// =====================================================================
#define KSTR 47
#define VSTR 288
#define ATT_SMEM ((Tt*KSTR + HDd*VSTR + 8*48 + 8*46) * 4)

__global__ __launch_bounds__(256, 2) void attn_k(const float* __restrict__ qkv,
                                                 __half* __restrict__ oh,
                                                 __half* __restrict__ ol) {
    extern __shared__ float smf[];
    float* Ksm = smf;
    float* Vt  = Ksm + Tt * KSTR;
    float* qsm = Vt + HDd * VSTR;
    float* osm = qsm + 8 * 48;

    const int h = blockIdx.x, b = blockIdx.y;
    const int tid = threadIdx.x, w = tid >> 5, lane = tid & 31;
    const float* base = qkv + (size_t)(b * Tt) * QKVW + h * HDd;

    for (int idx = tid; idx < Tt * HDd; idx += 256) {
        int s = idx / HDd, d = idx - s * HDd;
        const float* row = base + (size_t)s * QKVW;
        Ksm[s * KSTR + d] = row[HHd + d];
        Vt [d * VSTR + s] = row[2 * HHd + d];
    }
    for (int idx = tid; idx < HDd * (VSTR - Tt); idx += 256) {
        int d = idx / (VSTR - Tt), s = Tt + idx % (VSTR - Tt);
        Vt[d * VSTR + s] = 0.f;
    }
    __syncthreads();

    const float scale = rsqrtf((float)HDd);
    for (int t = w; t < Tt; t += 8) {
        for (int d = lane; d < HDd; d += 32)
            qsm[w * 48 + d] = base[(size_t)t * QKVW + d];
        __syncwarp();

        const int ngrp = (t >> 5) + 1;
        float p[9];
        float m = -1e30f;
        for (int i = 0; i < ngrp; i++) {
            int s = lane + (i << 5);
            float acc = -1e30f;
            if (s <= t) {
                float a = 0.f;
                #pragma unroll
                for (int d = 0; d < HDd; d++)
                    a += qsm[w * 48 + d] * Ksm[s * KSTR + d];
                acc = a * scale;
            }
            p[i] = acc;
            m = fmaxf(m, acc);
        }
        #pragma unroll
        for (int o = 16; o; o >>= 1) m = fmaxf(m, __shfl_xor_sync(0xFFFFFFFFu, m, o));

        float sum = 0.f;
        for (int i = 0; i < ngrp; i++) {
            float e = __expf(p[i] - m);
            p[i] = e; sum += e;
        }
        #pragma unroll
        for (int o = 16; o; o >>= 1) sum += __shfl_xor_sync(0xFFFFFFFFu, sum, o);
        const float inv = 1.f / sum;

        for (int d = 0; d < HDd; d++) {
            float part = 0.f;
            for (int i = 0; i < ngrp; i++)
                part += p[i] * Vt[d * VSTR + lane + (i << 5)];
            #pragma unroll
            for (int o = 16; o; o >>= 1) part += __shfl_xor_sync(0xFFFFFFFFu, part, o);
            if (lane == 0) osm[w * 46 + d] = part * inv;
        }
        __syncwarp();

        for (int d = lane; d < HDd; d += 32) {
            float v = osm[w * 46 + d];
            __half hi, lo;
            split2h(v, hi, lo);
            oh[(size_t)(b * Tt + t) * HHd + h * HDd + d] = hi;
            ol[(size_t)(b * Tt + t) * HHd + h * HDd + d] = lo;
        }
        __syncwarp();
    }
}

// ---- host ----
template <typename T>
static T* sym_addr(const void* sym) {
    void* p = nullptr;
    cudaGetSymbolAddress(&p, sym);
    return (T*)p;
}

static void tgemm128(const __half* Ah, const __half* Al, const __half* Bh,
                     const float* bias, const float* resid,
                     float* C, __half* Ch, __half* Cl,
                     int M, int N, int K, int ApK, int BpN, int ldc, int flags) {
    dim3 g((M + 127) / 128, (N + 127) / 128);
    hgemm_k<128><<<g, 256, HG_SMEM128>>>(Ah, Al, Bh, bias, resid, C, Ch, Cl,
                                         M, N, K, ApK, BpN, ldc, flags);
}
static void tgemm64(const __half* Ah, const __half* Al, const __half* Bh,
                    const float* bias, const float* resid,
                    float* C, __half* Ch, __half* Cl,
                    int M, int N, int K, int ApK, int BpN, int ldc, int flags) {
    dim3 g((M + 127) / 128, (N + 63) / 64);
    hgemm_k<64><<<g, 256, HG_SMEM64>>>(Ah, Al, Bh, bias, resid, C, Ch, Cl,
                                       M, N, K, ApK, BpN, ldc, flags);
}

extern "C" void kernel_launch(void* const* d_in, const int* in_sizes, int n_in,
                              void* d_out, int out_size) {
    const int*   idx     = (const int*)  d_in[0];
    const float* tok_emb = (const float*)d_in[1];
    const float* pos_emb = (const float*)d_in[2];
    const float* Wq      = (const float*)d_in[3];
    const float* Wk      = (const float*)d_in[4];
    const float* Wv      = (const float*)d_in[5];
    const float* Wproj   = (const float*)d_in[6];
    const float* bproj   = (const float*)d_in[7];
    const float* ln1_g   = (const float*)d_in[8];
    const float* ln1_b   = (const float*)d_in[9];
    const float* ln2_g   = (const float*)d_in[10];
    const float* ln2_b   = (const float*)d_in[11];
    const float* W1      = (const float*)d_in[12];
    const float* b1      = (const float*)d_in[13];
    const float* W2      = (const float*)d_in[14];
    const float* b2      = (const float*)d_in[15];
    const float* lnf_g   = (const float*)d_in[16];
    const float* lnf_b   = (const float*)d_in[17];
    const float* Wlm     = (const float*)d_in[18];
    const float* blm     = (const float*)d_in[19];
    float* out = (float*)d_out;

    static bool attr_set = false;
    if (!attr_set) {
        cudaFuncSetAttribute(hgemm_k<128>, cudaFuncAttributeMaxDynamicSharedMemorySize, HG_SMEM128);
        cudaFuncSetAttribute(hgemm_k<64>,  cudaFuncAttributeMaxDynamicSharedMemorySize, HG_SMEM64);
        cudaFuncSetAttribute(attn_k, cudaFuncAttributeMaxDynamicSharedMemorySize, ATT_SMEM);
        attr_set = true;
    }

    float* px   = sym_addr<float>(g_x);
    float* pqkv = sym_addr<float>(g_qkv);
    __half* phh  = sym_addr<__half>(g_hh);
    __half* phl  = sym_addr<__half>(g_hl);
    __half* poh  = sym_addr<__half>(g_oh);
    __half* pol  = sym_addr<__half>(g_ol);
    __half* pffh = sym_addr<__half>(g_ffh);
    __half* pffl = sym_addr<__half>(g_ffl);
    __half* pwq  = sym_addr<__half>(g_wqkv);
    __half* pwp  = sym_addr<__half>(g_wp);
    __half* pw1  = sym_addr<__half>(g_w1);
    __half* pw2  = sym_addr<__half>(g_w2);
    __half* pwlm = sym_addr<__half>(g_wlm);

    // ---- weight prep ----
    {
        int tot = Lx * Dd * QKVW;
        repack_qkv_k<<<(tot + 255) / 256, 256>>>(Wq, Wk, Wv, pwq);
        tot = Lx * HHd * PDd / 2;
        tohalf_pad_k<<<(tot + 255) / 256, 256>>>(Wproj, (__half2*)pwp, Lx * HHd, Dd, PDd / 2);
        tot = Lx * Dd * FFf / 2;
        tohalf_pad_k<<<(tot + 255) / 256, 256>>>(W1, (__half2*)pw1, Lx * Dd, FFf, FFf / 2);
        tot = Lx * FFf * PDd / 2;
        tohalf_pad_k<<<(tot + 255) / 256, 256>>>(W2, (__half2*)pw2, Lx * FFf, Dd, PDd / 2);
        tot = Dd * PVv / 2;
        tohalf_pad_k<<<(tot + 255) / 256, 256>>>(Wlm, (__half2*)pwlm, Dd, Vv, PVv / 2);
    }
    {
        const int total = NT * Dd;
        embed_k<<<(total + 255) / 256, 256>>>(idx, tok_emb, pos_emb);
    }

    dim3 gATT(Hh, Bbt);

    for (int l = 0; l < Lx; l++) {
        lnorm_split_k<<<NT, 256>>>(px, phh, phl, ln1_g + l * Dd, ln1_b + l * Dd);
        tgemm128(phh, phl, pwq + (size_t)l * Dd * QKVW,
                 nullptr, nullptr, pqkv, nullptr, nullptr,
                 NT, QKVW, Dd, PDd, QKVW, QKVW, 0);
        attn_k<<<gATT, 256, ATT_SMEM>>>(pqkv, poh, pol);
        // proj: N=726 -> BN64 (396 blocks, 1.34 waves)
        tgemm64(poh, pol, pwp + (size_t)l * HHd * PDd,
                bproj + l * Dd, px, px, nullptr, nullptr,
                NT, Dd, HHd, HHd, PDd, Dd, F_BIAS | F_RESID);
        lnorm_split_k<<<NT, 256>>>(px, phh, phl, ln2_g + l * Dd, ln2_b + l * Dd);
        tgemm128(phh, phl, pw1 + (size_t)l * Dd * FFf,
                 b1 + (size_t)l * FFf, nullptr, nullptr, pffh, pffl,
                 NT, FFf, Dd, PDd, FFf, FFf, F_BIAS | F_RELU | F_SPLIT);
        // ff2: N=726 -> BN64
        tgemm64(pffh, pffl, pw2 + (size_t)l * FFf * PDd,
                b2 + l * Dd, px, px, nullptr, nullptr,
                NT, Dd, FFf, FFf, PDd, Dd, F_BIAS | F_RESID);
    }

    lnorm_split_k<<<NT, 256>>>(px, phh, phl, lnf_g, lnf_b);
    tgemm128(phh, phl, pwlm, blm, nullptr, out, nullptr, nullptr,
             NT, Vv, Dd, PDd, PVv, Vv, F_BIAS | F_NOLO);
}

// round 15
// speedup vs baseline: 1.0429x; 1.0056x over previous
#include <cuda_runtime.h>
#include <cuda_fp16.h>
#include <stdint.h>
#include <math.h>

// ---- problem constants ----
#define Lx   12
#define Dd   726
#define Hh   16
#define HDd  45
#define Tt   258
#define Vv   50257
#define Bbt  16
#define FFf  2904           // 4*D
#define NT   (Bbt*Tt)       // 4128 tokens
#define HHd  (Hh*HDd)       // 720
#define QKVW (3*HHd)        // 2160

#define PDd  728            // Dd padded to 8
#define PVv  50264          // Vv padded to 8

#define F_BIAS  1
#define F_RELU  2
#define F_RESID 4
#define F_SPLIT 8
#define F_NOLO  16          // skip A-lo plane (single-MMA path)

// ---- fp32 scratch ----
__device__ float g_x   [NT*Dd];
__device__ float g_qkv [NT*QKVW];

// ---- fp16 planes: activations hi+lo, weights hi only ----
__device__ __half g_hh [NT*PDd],  g_hl [NT*PDd];     // LN output
__device__ __half g_oh [NT*HHd],  g_ol [NT*HHd];     // attn output
__device__ __half g_ffh[NT*FFf],  g_ffl[NT*FFf];     // relu(ff1)
__device__ __half g_wqkv[Lx*Dd*QKVW];
__device__ __half g_wp  [Lx*HHd*PDd];
__device__ __half g_w1  [Lx*Dd*FFf];
__device__ __half g_w2  [Lx*FFf*PDd];
__device__ __half g_wlm [Dd*PVv];

// =====================================================================
// helpers
// =====================================================================
__device__ __forceinline__ uint32_t smem_u32(const void* p) {
    uint32_t a;
    asm("{ .reg .u64 t; cvta.to.shared.u64 t, %1; cvt.u32.u64 %0, t; }"
        : "=r"(a) : "l"(p));
    return a;
}
__device__ __forceinline__ void ldsm4(uint32_t& r0, uint32_t& r1,
                                      uint32_t& r2, uint32_t& r3, uint32_t addr) {
    asm volatile("ldmatrix.sync.aligned.m8n8.x4.shared.b16 {%0,%1,%2,%3}, [%4];"
                 : "=r"(r0), "=r"(r1), "=r"(r2), "=r"(r3) : "r"(addr));
}
__device__ __forceinline__ void ldsm4t(uint32_t& r0, uint32_t& r1,
                                       uint32_t& r2, uint32_t& r3, uint32_t addr) {
    asm volatile("ldmatrix.sync.aligned.m8n8.x4.trans.shared.b16 {%0,%1,%2,%3}, [%4];"
                 : "=r"(r0), "=r"(r1), "=r"(r2), "=r"(r3) : "r"(addr));
}
__device__ __forceinline__ void mma16816(float* c, const uint32_t* a,
                                         uint32_t b0, uint32_t b1) {
    asm volatile(
        "mma.sync.aligned.m16n8k16.row.col.f32.f16.f16.f32 "
        "{%0,%1,%2,%3},{%4,%5,%6,%7},{%8,%9},{%0,%1,%2,%3};"
        : "+f"(c[0]), "+f"(c[1]), "+f"(c[2]), "+f"(c[3])
        : "r"(a[0]), "r"(a[1]), "r"(a[2]), "r"(a[3]), "r"(b0), "r"(b1));
}
__device__ __forceinline__ void cpa16(uint32_t dst, const void* src, int bytes) {
    asm volatile("cp.async.cg.shared.global [%0], [%1], 16, %2;"
                 :: "r"(dst), "l"(src), "r"(bytes));
}
__device__ __forceinline__ void cpa_commit() {
    asm volatile("cp.async.commit_group;" ::: "memory");
}
__device__ __forceinline__ void cpa_wait0() {
    asm volatile("cp.async.wait_group 0;" ::: "memory");
}
__device__ __forceinline__ void split2h(float v, __half& h, __half& l) {
    h = __float2half_rn(v);
    l = __float2half_rn(v - __half2float(h));
}

// =====================================================================
// GEMM template: C[M,N] = A[M,K] @ B[K,N]; A hi(+lo) fp16, B fp16.
// <128,64>: CTA 128x128, stage 48KB, 2 CTA/SM (register-capped).
// <64,32>:  CTA 128x64,  stage 20KB, 3 CTA/SM (84 regs), KCH=32.
// 8 warps: 4m x 2n; warp tile 32 x (BN/2). One __syncthreads per chunk.
// =====================================================================
template<int BN, int KCHt>
__global__ __launch_bounds__(256, (BN == 128 ? 2 : 3)) void hgemm_k(
    const __half* __restrict__ Ah, const __half* __restrict__ Al,
    const __half* __restrict__ Bh,
    const float* __restrict__ bias, const float* __restrict__ resid,
    float* __restrict__ C, __half* __restrict__ Ch, __half* __restrict__ Cl,
    int M, int N, int K, int ApK, int BpN, int ldc, int flags)
{
    constexpr int NT2  = BN / 32;              // B 16-col groups per warp
    constexpr int KSN  = KCHt / 16;            // k-steps per chunk
    constexpr int ARB  = KCHt * 2;             // A row bytes (128 / 64)
    constexpr int BRB  = BN * 2;               // B row bytes (256 / 128)
    constexpr int ASEG = ARB / 16;             // A 16B segs per row
    constexpr int BSEG = BN / 8;               // B 16B segs per row
    constexpr uint32_t AMS  = (ARB == 128) ? 0x70u : 0x30u;
    constexpr uint32_t SLO  = (uint32_t)(128 * ARB);      // A-lo offset
    constexpr uint32_t SB   = 2u * SLO;                   // B offset
    constexpr uint32_t STGT = SB + (uint32_t)(KCHt * BN * 2);

    extern __shared__ __align__(1024) char smraw[];
    const uint32_t sbase = smem_u32(smraw);

    const int tid  = threadIdx.x;
    const int wid  = tid >> 5;
    const int lane = tid & 31;
    const int warp_m = wid & 3;
    const int warp_n = wid >> 2;

    const int m0 = blockIdx.x << 7;
    const int n0 = blockIdx.y * BN;
    const int nCh = (K + KCHt - 1) / KCHt;
    const bool uselo = !(flags & F_NOLO);

    float c[2][2 * NT2][4];
    #pragma unroll
    for (int i = 0; i < 2; i++)
        #pragma unroll
        for (int j = 0; j < 2 * NT2; j++)
            #pragma unroll
            for (int q = 0; q < 4; q++) c[i][j][q] = 0.f;

    // A: unswizzled base + per-row mask; XOR applied AFTER the ks add
    // (ks*32 touches masked bits for both ARB classes).
    uint32_t abase[2], amask[2];
    #pragma unroll
    for (int mt = 0; mt < 2; mt++) {
        uint32_t o = (uint32_t)((warp_m * 32 + mt * 16 + (lane & 15)) * ARB
                                + ((lane >> 4) << 4));
        abase[mt] = o;
        amask[mt] = (o >> 3) & AMS;
    }
    // B fragment byte offsets (warp covers BN/2 cols = BN bytes);
    // ks step (16*BRB) is above swizzle-source bits -> additive.
    uint32_t boff[NT2];
    #pragma unroll
    for (int nt2 = 0; nt2 < NT2; nt2++) {
        uint32_t o = (uint32_t)((((lane >> 3) & 1) * 8 + (lane & 7)) * BRB
                                + warp_n * BN + nt2 * 32 + ((lane >> 4) << 4));
        if (BRB == 256) o ^= (o >> 4) & 0xF0u;
        else            o ^= (o >> 3) & 0x70u;
        boff[nt2] = o;
    }

    auto issue = [&](int ch) {
        const uint32_t st = sbase + (uint32_t)(ch & 1) * STGT;
        const int k0 = ch * KCHt;
        // A hi(+lo): 128 rows x ASEG segs of 16B
        #pragma unroll
        for (int i = 0; i < (128 * ASEG) / 256; i++) {
            int g = tid + (i << 8);
            int seg = g & (ASEG - 1), r = g / ASEG;
            int m = m0 + r, k = k0 + (seg << 3);
            int bytes = (m < M && k < ApK) ? 16 : 0;
            size_t gi = (size_t)m * ApK + k;
            uint32_t o = (uint32_t)(r * ARB + (seg << 4));
            o ^= (o >> 3) & AMS;
            cpa16(st + o, bytes ? (const void*)(Ah + gi) : (const void*)Ah, bytes);
            if (uselo)
                cpa16(st + SLO + o, bytes ? (const void*)(Al + gi) : (const void*)Al, bytes);
        }
        // B: KCHt rows x BSEG segs of 16B
        #pragma unroll
        for (int i = 0; i < (KCHt * BSEG) / 256; i++) {
            int g = tid + (i << 8);
            int seg = g & (BSEG - 1), r = g / BSEG;
            int k = k0 + r, n = n0 + (seg << 3);
            int bytes = (k < K && n < BpN) ? 16 : 0;
            const void* p = bytes ? (const void*)(Bh + (size_t)k * BpN + n)
                                  : (const void*)Bh;
            uint32_t o = (uint32_t)(r * BRB + (seg << 4));
            if (BRB == 256) o ^= (o >> 4) & 0xF0u;
            else            o ^= (o >> 3) & 0x70u;
            cpa16(st + SB + o, p, bytes);
        }
    };

    issue(0);
    cpa_commit();

    for (int ch = 0; ch < nCh; ch++) {
        cpa_wait0();
        __syncthreads();

        if (ch + 1 < nCh) {
            issue(ch + 1);
            cpa_commit();
        }

        const uint32_t st = sbase + (uint32_t)(ch & 1) * STGT;
        #pragma unroll
        for (int ks = 0; ks < KSN; ks++) {
            uint32_t ahi[2][4], alo[2][4];
            #pragma unroll
            for (int mt = 0; mt < 2; mt++) {
                uint32_t ad = st + ((abase[mt] + (uint32_t)(ks * 32)) ^ amask[mt]);
                ldsm4(ahi[mt][0], ahi[mt][1], ahi[mt][2], ahi[mt][3], ad);
                if (uselo)
                    ldsm4(alo[mt][0], alo[mt][1], alo[mt][2], alo[mt][3], ad + SLO);
            }
            #pragma unroll
            for (int nt2 = 0; nt2 < NT2; nt2++) {
                uint32_t bh[4];
                ldsm4t(bh[0], bh[1], bh[2], bh[3],
                       st + SB + boff[nt2] + (uint32_t)(ks * 16 * BRB));
                #pragma unroll
                for (int hh = 0; hh < 2; hh++) {
                    const int nt = nt2 * 2 + hh;
                    #pragma unroll
                    for (int mt = 0; mt < 2; mt++) {
                        mma16816(c[mt][nt], ahi[mt], bh[hh * 2], bh[hh * 2 + 1]);
                        if (uselo)
                            mma16816(c[mt][nt], alo[mt], bh[hh * 2], bh[hh * 2 + 1]);
                    }
                }
            }
        }
    }

    // ---- epilogue ----
    #pragma unroll
    for (int mt = 0; mt < 2; mt++) {
        #pragma unroll
        for (int nt = 0; nt < 2 * NT2; nt++) {
            int rb = m0 + warp_m * 32 + mt * 16 + (lane >> 2);
            int nc = n0 + warp_n * (BN / 2) + nt * 8 + ((lane & 3) << 1);
            #pragma unroll
            for (int half = 0; half < 2; half++) {
                int m = rb + half * 8;
                if (m < M) {
                    #pragma unroll
                    for (int j = 0; j < 2; j++) {
                        int n = nc + j;
                        if (n < N) {
                            float v = c[mt][nt][half * 2 + j];
                            if (flags & F_BIAS)  v += bias[n];
                            if (flags & F_RESID) v += resid[(size_t)m * ldc + n];
                            if (flags & F_RELU)  v = fmaxf(v, 0.f);
                            if (flags & F_SPLIT) {
                                __half h, l;
                                split2h(v, h, l);
                                Ch[(size_t)m * ldc + n] = h;
                                Cl[(size_t)m * ldc + n] = l;
                            } else {
                                C[(size_t)m * ldc + n] = v;
                            }
                        }
                    }
                }
            }
        }
    }
}

#define HG_SMEM128 (2 * (2 * 128 * 128 + 64 * 128 * 2))   // 98304
#define HG_SMEM64  (2 * (2 * 128 * 64  + 32 * 64  * 2))   // 40960

// =====================================================================
// weight prep kernels
// =====================================================================
__global__ void repack_qkv_k(const float* __restrict__ Wq,
                             const float* __restrict__ Wk,
                             const float* __restrict__ Wv,
                             __half* __restrict__ d) {
    int i = blockIdx.x * blockDim.x + threadIdx.x;
    const int total = Lx * Dd * QKVW;
    if (i >= total) return;
    int j    = i % QKVW;
    int rest = i / QKVW;
    int dd   = rest % Dd;
    int l    = rest / Dd;
    int sel = j / HHd;
    int n   = j % HHd;
    int h  = n / HDd;
    int kk = n % HDd;
    const float* src = (sel == 0) ? Wq : (sel == 1) ? Wk : Wv;
    d[i] = __float2half_rn(src[((l * Hh + h) * Dd + dd) * HDd + kk]);
}

// two tensors per launch (keeps launch count low so ncu -s 5 hits hgemm)
__global__ void tohalf2_k(const float* __restrict__ s1, __half2* __restrict__ d1,
                          int R1, int C1, int Cp21,
                          const float* __restrict__ s2, __half2* __restrict__ d2,
                          int R2, int C2, int Cp22) {
    int i = blockIdx.x * blockDim.x + threadIdx.x;
    int n1 = R1 * Cp21;
    if (i < n1) {
        int r = i / Cp21, c2 = (i - r * Cp21) << 1;
        const float* row = s1 + (size_t)r * C1;
        float v0 = (c2     < C1) ? row[c2]     : 0.f;
        float v1 = (c2 + 1 < C1) ? row[c2 + 1] : 0.f;
        d1[i] = __floats2half2_rn(v0, v1);
    } else {
        int j = i - n1;
        if (j >= R2 * Cp22) return;
        int r = j / Cp22, c2 = (j - r * Cp22) << 1;
        const float* row = s2 + (size_t)r * C2;
        float v0 = (c2     < C2) ? row[c2]     : 0.f;
        float v1 = (c2 + 1 < C2) ? row[c2 + 1] : 0.f;
        d2[j] = __floats2half2_rn(v0, v1);
    }
}

// ---- embedding ----
__global__ void embed_k(const int* __restrict__ idx,
                        const float* __restrict__ tok,
                        const float* __restrict__ pos) {
    int i = blockIdx.x * blockDim.x + threadIdx.x;
    if (i >= NT * Dd) return;
    int d = i % Dd;
    int n = i / Dd;
    int t = n % Tt;
    g_x[i] = tok[idx[n] * Dd + d] + pos[t * Dd + d];
}

// ---- layernorm -> hi/lo planes ----
__global__ void lnorm_split_k(const float* __restrict__ in,
                              __half* __restrict__ oh,
                              __half* __restrict__ ol,
                              const float* __restrict__ g, const float* __restrict__ b) {
    int row = blockIdx.x;
    const float* xr = in + (size_t)row * Dd;
    __shared__ float r1[256];
    __shared__ float r2[256];
    float s = 0.f, ss = 0.f;
    for (int d = threadIdx.x; d < Dd; d += 256) {
        float v = xr[d];
        s += v; ss += v * v;
    }
    r1[threadIdx.x] = s; r2[threadIdx.x] = ss;
    __syncthreads();
    for (int o = 128; o > 0; o >>= 1) {
        if (threadIdx.x < o) { r1[threadIdx.x] += r1[threadIdx.x + o]; r2[threadIdx.x] += r2[threadIdx.x + o]; }
        __syncthreads();
    }
    float mean = r1[0] / Dd;
    float var  = r2[0] / Dd - mean * mean;
    float inv  = rsqrtf(var + 1e-5f);
    for (int d = threadIdx.x; d < PDd; d += 256) {
        float v = 0.f;
        if (d < Dd) v = (xr[d] - mean) * inv * g[d] + b[d];
        __half hi, lo;
        split2h(v, hi, lo);
        oh[(size_t)row * PDd + d] = hi;
        ol[(size_t)row * PDd + d] = lo;
    }
}

// =====================================================================
// attention (K,V staged in smem once per (b,h))
// =====================================================================
#define KSTR 47
#define VSTR 288
#define ATT_SMEM ((Tt*KSTR + HDd*VSTR + 8*48 + 8*46) * 4)

__global__ __launch_bounds__(256, 2) void attn_k(const float* __restrict__ qkv,
                                                 __half* __restrict__ oh,
                                                 __half* __restrict__ ol) {
    extern __shared__ float smf[];
    float* Ksm = smf;
    float* Vt  = Ksm + Tt * KSTR;
    float* qsm = Vt + HDd * VSTR;
    float* osm = qsm + 8 * 48;

    const int h = blockIdx.x, b = blockIdx.y;
    const int tid = threadIdx.x, w = tid >> 5, lane = tid & 31;
    const float* base = qkv + (size_t)(b * Tt) * QKVW + h * HDd;

    for (int idx = tid; idx < Tt * HDd; idx += 256) {
        int s = idx / HDd, d = idx - s * HDd;
        const float* row = base + (size_t)s * QKVW;
        Ksm[s * KSTR + d] = row[HHd + d];
        Vt [d * VSTR + s] = row[2 * HHd + d];
    }
    for (int idx = tid; idx < HDd * (VSTR - Tt); idx += 256) {
        int d = idx / (VSTR - Tt), s = Tt + idx % (VSTR - Tt);
        Vt[d * VSTR + s] = 0.f;
    }
    __syncthreads();

    const float scale = rsqrtf((float)HDd);
    for (int t = w; t < Tt; t += 8) {
        for (int d = lane; d < HDd; d += 32)
            qsm[w * 48 + d] = base[(size_t)t * QKVW + d];
        __syncwarp();

        const int ngrp = (t >> 5) + 1;
        float p[9];
        float m = -1e30f;
        for (int i = 0; i < ngrp; i++) {
            int s = lane + (i << 5);
            float acc = -1e30f;
            if (s <= t) {
                float a = 0.f;
                #pragma unroll
                for (int d = 0; d < HDd; d++)
                    a += qsm[w * 48 + d] * Ksm[s * KSTR + d];
                acc = a * scale;
            }
            p[i] = acc;
            m = fmaxf(m, acc);
        }
        #pragma unroll
        for (int o = 16; o; o >>= 1) m = fmaxf(m, __shfl_xor_sync(0xFFFFFFFFu, m, o));

        float sum = 0.f;
        for (int i = 0; i < ngrp; i++) {
            float e = __expf(p[i] - m);
            p[i] = e; sum += e;
        }
        #pragma unroll
        for (int o = 16; o; o >>= 1) sum += __shfl_xor_sync(0xFFFFFFFFu, sum, o);
        const float inv = 1.f / sum;

        for (int d = 0; d < HDd; d++) {
            float part = 0.f;
            for (int i = 0; i < ngrp; i++)
                part += p[i] * Vt[d * VSTR + lane + (i << 5)];
            #pragma unroll
            for (int o = 16; o; o >>= 1) part += __shfl_xor_sync(0xFFFFFFFFu, part, o);
            if (lane == 0) osm[w * 46 + d] = part * inv;
        }
        __syncwarp();

        for (int d = lane; d < HDd; d += 32) {
            float v = osm[w * 46 + d];
            __half hi, lo;
            split2h(v, hi, lo);
            oh[(size_t)(b * Tt + t) * HHd + h * HDd + d] = hi;
            ol[(size_t)(b * Tt + t) * HHd + h * HDd + d] = lo;
        }
        __syncwarp();
    }
}

// ---- host ----
template <typename T>
static T* sym_addr(const void* sym) {
    void* p = nullptr;
    cudaGetSymbolAddress(&p, sym);
    return (T*)p;
}

static void tgemm128(const __half* Ah, const __half* Al, const __half* Bh,
                     const float* bias, const float* resid,
                     float* C, __half* Ch, __half* Cl,
                     int M, int N, int K, int ApK, int BpN, int ldc, int flags) {
    dim3 g((M + 127) / 128, (N + 127) / 128);
    hgemm_k<128, 64><<<g, 256, HG_SMEM128>>>(Ah, Al, Bh, bias, resid, C, Ch, Cl,
                                             M, N, K, ApK, BpN, ldc, flags);
}
static void tgemm64(const __half* Ah, const __half* Al, const __half* Bh,
                    const float* bias, const float* resid,
                    float* C, __half* Ch, __half* Cl,
                    int M, int N, int K, int ApK, int BpN, int ldc, int flags) {
    dim3 g((M + 127) / 128, (N + 63) / 64);
    hgemm_k<64, 32><<<g, 256, HG_SMEM64>>>(Ah, Al, Bh, bias, resid, C, Ch, Cl,
                                           M, N, K, ApK, BpN, ldc, flags);
}

extern "C" void kernel_launch(void* const* d_in, const int* in_sizes, int n_in,
                              void* d_out, int out_size) {
    const int*   idx     = (const int*)  d_in[0];
    const float* tok_emb = (const float*)d_in[1];
    const float* pos_emb = (const float*)d_in[2];
    const float* Wq      = (const float*)d_in[3];
    const float* Wk      = (const float*)d_in[4];
    const float* Wv      = (const float*)d_in[5];
    const float* Wproj   = (const float*)d_in[6];
    const float* bproj   = (const float*)d_in[7];
    const float* ln1_g   = (const float*)d_in[8];
    const float* ln1_b   = (const float*)d_in[9];
    const float* ln2_g   = (const float*)d_in[10];
    const float* ln2_b   = (const float*)d_in[11];
    const float* W1      = (const float*)d_in[12];
    const float* b1      = (const float*)d_in[13];
    const float* W2      = (const float*)d_in[14];
    const float* b2      = (const float*)d_in[15];
    const float* lnf_g   = (const float*)d_in[16];
    const float* lnf_b   = (const float*)d_in[17];
    const float* Wlm     = (const float*)d_in[18];
    const float* blm     = (const float*)d_in[19];
    float* out = (float*)d_out;

    static bool attr_set = false;
    if (!attr_set) {
        cudaFuncSetAttribute((const void*)hgemm_k<128, 64>,
                             cudaFuncAttributeMaxDynamicSharedMemorySize, HG_SMEM128);
        cudaFuncSetAttribute((const void*)hgemm_k<64, 32>,
                             cudaFuncAttributeMaxDynamicSharedMemorySize, HG_SMEM64);
        cudaFuncSetAttribute(attn_k, cudaFuncAttributeMaxDynamicSharedMemorySize, ATT_SMEM);
        attr_set = true;
    }

    float* px   = sym_addr<float>(g_x);
    float* pqkv = sym_addr<float>(g_qkv);
    __half* phh  = sym_addr<__half>(g_hh);
    __half* phl  = sym_addr<__half>(g_hl);
    __half* poh  = sym_addr<__half>(g_oh);
    __half* pol  = sym_addr<__half>(g_ol);
    __half* pffh = sym_addr<__half>(g_ffh);
    __half* pffl = sym_addr<__half>(g_ffl);
    __half* pwq  = sym_addr<__half>(g_wqkv);
    __half* pwp  = sym_addr<__half>(g_wp);
    __half* pw1  = sym_addr<__half>(g_w1);
    __half* pw2  = sym_addr<__half>(g_w2);
    __half* pwlm = sym_addr<__half>(g_wlm);

    // ---- weight prep (launches 0-2) + embed (3) ----
    {
        int tot = Lx * Dd * QKVW;
        repack_qkv_k<<<(tot + 255) / 256, 256>>>(Wq, Wk, Wv, pwq);   // #0

        int nA = Lx * HHd * PDd / 2, nB = Lx * Dd * FFf / 2;
        tohalf2_k<<<(nA + nB + 255) / 256, 256>>>(                   // #1
            Wproj, (__half2*)pwp, Lx * HHd, Dd, PDd / 2,
            W1,    (__half2*)pw1, Lx * Dd,  FFf, FFf / 2);

        int nC = Lx * FFf * PDd / 2, nD = Dd * PVv / 2;
        tohalf2_k<<<(nC + nD + 255) / 256, 256>>>(                   // #2
            W2,  (__half2*)pw2,  Lx * FFf, Dd, PDd / 2,
            Wlm, (__half2*)pwlm, Dd,       Vv, PVv / 2);

        embed_k<<<(NT * Dd + 255) / 256, 256>>>(idx, tok_emb, pos_emb);  // #3
    }

    dim3 gATT(Hh, Bbt);

    for (int l = 0; l < Lx; l++) {
        lnorm_split_k<<<NT, 256>>>(px, phh, phl, ln1_g + l * Dd, ln1_b + l * Dd);  // #4 (l=0)
        tgemm128(phh, phl, pwq + (size_t)l * Dd * QKVW,                            // #5 (l=0) <- ncu
                 nullptr, nullptr, pqkv, nullptr, nullptr,
                 NT, QKVW, Dd, PDd, QKVW, QKVW, 0);
        attn_k<<<gATT, 256, ATT_SMEM>>>(pqkv, poh, pol);
        // proj: N=726 -> BN64/KCH32, 3 CTA/SM, single wave (396/444)
        tgemm64(poh, pol, pwp + (size_t)l * HHd * PDd,
                bproj + l * Dd, px, px, nullptr, nullptr,
                NT, Dd, HHd, HHd, PDd, Dd, F_BIAS | F_RESID);
        lnorm_split_k<<<NT, 256>>>(px, phh, phl, ln2_g + l * Dd, ln2_b + l * Dd);
        tgemm128(phh, phl, pw1 + (size_t)l * Dd * FFf,
                 b1 + (size_t)l * FFf, nullptr, nullptr, pffh, pffl,
                 NT, FFf, Dd, PDd, FFf, FFf, F_BIAS | F_RELU | F_SPLIT);
        // ff2: N=726 -> BN64/KCH32
        tgemm64(pffh, pffl, pw2 + (size_t)l * FFf * PDd,
                b2 + l * Dd, px, px, nullptr, nullptr,
                NT, Dd, FFf, FFf, PDd, Dd, F_BIAS | F_RESID);
    }

    lnorm_split_k<<<NT, 256>>>(px, phh, phl, lnf_g, lnf_b);
    tgemm128(phh, phl, pwlm, blm, nullptr, out, nullptr, nullptr,
             NT, Vv, Dd, PDd, PVv, Vv, F_BIAS | F_NOLO);
}

// round 16
// speedup vs baseline: 1.0583x; 1.0147x over previous
#include <cuda_runtime.h>
#include <cuda_fp16.h>
#include <stdint.h>
#include <math.h>

// ---- problem constants ----
#define Lx   12
#define Dd   726
#define Hh   16
#define HDd  45
#define Tt   258
#define Vv   50257
#define Bbt  16
#define FFf  2904           // 4*D
#define NT   (Bbt*Tt)       // 4128 tokens
#define HHd  (Hh*HDd)       // 720
#define QKVW (3*HHd)        // 2160

#define PDd  728            // Dd padded to 8
#define PVv  50264          // Vv padded to 8

#define F_BIAS  1
#define F_RELU  2
#define F_RESID 4
#define F_SPLIT 8
#define F_NOLO  16          // skip A-lo plane (single-MMA path)

// ---- fp32 scratch ----
__device__ float g_x   [NT*Dd];
__device__ float g_qkv [NT*QKVW];

// ---- fp16 planes ----
__device__ __half g_hh [NT*PDd],  g_hl [NT*PDd];     // LN output
__device__ __half g_oh [NT*HHd],  g_ol [NT*HHd];     // attn output
__device__ __half g_ffh[NT*FFf];                     // relu(ff1), hi only
__device__ __half g_wqkv[Lx*Dd*QKVW];
__device__ __half g_wp  [Lx*HHd*PDd];
__device__ __half g_w1  [Lx*Dd*FFf];
__device__ __half g_w2  [Lx*FFf*PDd];
__device__ __half g_wlm [Dd*PVv];

// =====================================================================
// helpers
// =====================================================================
__device__ __forceinline__ uint32_t smem_u32(const void* p) {
    uint32_t a;
    asm("{ .reg .u64 t; cvta.to.shared.u64 t, %1; cvt.u32.u64 %0, t; }"
        : "=r"(a) : "l"(p));
    return a;
}
__device__ __forceinline__ void ldsm4(uint32_t& r0, uint32_t& r1,
                                      uint32_t& r2, uint32_t& r3, uint32_t addr) {
    asm volatile("ldmatrix.sync.aligned.m8n8.x4.shared.b16 {%0,%1,%2,%3}, [%4];"
                 : "=r"(r0), "=r"(r1), "=r"(r2), "=r"(r3) : "r"(addr));
}
__device__ __forceinline__ void ldsm4t(uint32_t& r0, uint32_t& r1,
                                       uint32_t& r2, uint32_t& r3, uint32_t addr) {
    asm volatile("ldmatrix.sync.aligned.m8n8.x4.trans.shared.b16 {%0,%1,%2,%3}, [%4];"
                 : "=r"(r0), "=r"(r1), "=r"(r2), "=r"(r3) : "r"(addr));
}
__device__ __forceinline__ void mma16816(float* c, const uint32_t* a,
                                         uint32_t b0, uint32_t b1) {
    asm volatile(
        "mma.sync.aligned.m16n8k16.row.col.f32.f16.f16.f32 "
        "{%0,%1,%2,%3},{%4,%5,%6,%7},{%8,%9},{%0,%1,%2,%3};"
        : "+f"(c[0]), "+f"(c[1]), "+f"(c[2]), "+f"(c[3])
        : "r"(a[0]), "r"(a[1]), "r"(a[2]), "r"(a[3]), "r"(b0), "r"(b1));
}
__device__ __forceinline__ void cpa16(uint32_t dst, const void* src, int bytes) {
    asm volatile("cp.async.cg.shared.global [%0], [%1], 16, %2;"
                 :: "r"(dst), "l"(src), "r"(bytes));
}
__device__ __forceinline__ void cpa_commit() {
    asm volatile("cp.async.commit_group;" ::: "memory");
}
__device__ __forceinline__ void cpa_wait0() {
    asm volatile("cp.async.wait_group 0;" ::: "memory");
}
__device__ __forceinline__ void split2h(float v, __half& h, __half& l) {
    h = __float2half_rn(v);
    l = __float2half_rn(v - __half2float(h));
}

// =====================================================================
// GEMM template (as round 15; epilogue writes lo plane only if Cl)
// =====================================================================
template<int BN, int KCHt>
__global__ __launch_bounds__(256, (BN == 128 ? 2 : 3)) void hgemm_k(
    const __half* __restrict__ Ah, const __half* __restrict__ Al,
    const __half* __restrict__ Bh,
    const float* __restrict__ bias, const float* __restrict__ resid,
    float* __restrict__ C, __half* __restrict__ Ch, __half* __restrict__ Cl,
    int M, int N, int K, int ApK, int BpN, int ldc, int flags)
{
    constexpr int NT2  = BN / 32;
    constexpr int KSN  = KCHt / 16;
    constexpr int ARB  = KCHt * 2;
    constexpr int BRB  = BN * 2;
    constexpr int ASEG = ARB / 16;
    constexpr int BSEG = BN / 8;
    constexpr uint32_t AMS  = (ARB == 128) ? 0x70u : 0x30u;
    constexpr uint32_t SLO  = (uint32_t)(128 * ARB);
    constexpr uint32_t SB   = 2u * SLO;
    constexpr uint32_t STGT = SB + (uint32_t)(KCHt * BN * 2);

    extern __shared__ __align__(1024) char smraw[];
    const uint32_t sbase = smem_u32(smraw);

    const int tid  = threadIdx.x;
    const int wid  = tid >> 5;
    const int lane = tid & 31;
    const int warp_m = wid & 3;
    const int warp_n = wid >> 2;

    const int m0 = blockIdx.x << 7;
    const int n0 = blockIdx.y * BN;
    const int nCh = (K + KCHt - 1) / KCHt;
    const bool uselo = !(flags & F_NOLO);

    float c[2][2 * NT2][4];
    #pragma unroll
    for (int i = 0; i < 2; i++)
        #pragma unroll
        for (int j = 0; j < 2 * NT2; j++)
            #pragma unroll
            for (int q = 0; q < 4; q++) c[i][j][q] = 0.f;

    uint32_t abase[2], amask[2];
    #pragma unroll
    for (int mt = 0; mt < 2; mt++) {
        uint32_t o = (uint32_t)((warp_m * 32 + mt * 16 + (lane & 15)) * ARB
                                + ((lane >> 4) << 4));
        abase[mt] = o;
        amask[mt] = (o >> 3) & AMS;
    }
    uint32_t boff[NT2];
    #pragma unroll
    for (int nt2 = 0; nt2 < NT2; nt2++) {
        uint32_t o = (uint32_t)((((lane >> 3) & 1) * 8 + (lane & 7)) * BRB
                                + warp_n * BN + nt2 * 32 + ((lane >> 4) << 4));
        if (BRB == 256) o ^= (o >> 4) & 0xF0u;
        else            o ^= (o >> 3) & 0x70u;
        boff[nt2] = o;
    }

    auto issue = [&](int ch) {
        const uint32_t st = sbase + (uint32_t)(ch & 1) * STGT;
        const int k0 = ch * KCHt;
        #pragma unroll
        for (int i = 0; i < (128 * ASEG) / 256; i++) {
            int g = tid + (i << 8);
            int seg = g & (ASEG - 1), r = g / ASEG;
            int m = m0 + r, k = k0 + (seg << 3);
            int bytes = (m < M && k < ApK) ? 16 : 0;
            size_t gi = (size_t)m * ApK + k;
            uint32_t o = (uint32_t)(r * ARB + (seg << 4));
            o ^= (o >> 3) & AMS;
            cpa16(st + o, bytes ? (const void*)(Ah + gi) : (const void*)Ah, bytes);
            if (uselo)
                cpa16(st + SLO + o, bytes ? (const void*)(Al + gi) : (const void*)Al, bytes);
        }
        #pragma unroll
        for (int i = 0; i < (KCHt * BSEG) / 256; i++) {
            int g = tid + (i << 8);
            int seg = g & (BSEG - 1), r = g / BSEG;
            int k = k0 + r, n = n0 + (seg << 3);
            int bytes = (k < K && n < BpN) ? 16 : 0;
            const void* p = bytes ? (const void*)(Bh + (size_t)k * BpN + n)
                                  : (const void*)Bh;
            uint32_t o = (uint32_t)(r * BRB + (seg << 4));
            if (BRB == 256) o ^= (o >> 4) & 0xF0u;
            else            o ^= (o >> 3) & 0x70u;
            cpa16(st + SB + o, p, bytes);
        }
    };

    issue(0);
    cpa_commit();

    for (int ch = 0; ch < nCh; ch++) {
        cpa_wait0();
        __syncthreads();

        if (ch + 1 < nCh) {
            issue(ch + 1);
            cpa_commit();
        }

        const uint32_t st = sbase + (uint32_t)(ch & 1) * STGT;
        #pragma unroll
        for (int ks = 0; ks < KSN; ks++) {
            uint32_t ahi[2][4], alo[2][4];
            #pragma unroll
            for (int mt = 0; mt < 2; mt++) {
                uint32_t ad = st + ((abase[mt] + (uint32_t)(ks * 32)) ^ amask[mt]);
                ldsm4(ahi[mt][0], ahi[mt][1], ahi[mt][2], ahi[mt][3], ad);
                if (uselo)
                    ldsm4(alo[mt][0], alo[mt][1], alo[mt][2], alo[mt][3], ad + SLO);
            }
            #pragma unroll
            for (int nt2 = 0; nt2 < NT2; nt2++) {
                uint32_t bh[4];
                ldsm4t(bh[0], bh[1], bh[2], bh[3],
                       st + SB + boff[nt2] + (uint32_t)(ks * 16 * BRB));
                #pragma unroll
                for (int hh = 0; hh < 2; hh++) {
                    const int nt = nt2 * 2 + hh;
                    #pragma unroll
                    for (int mt = 0; mt < 2; mt++) {
                        mma16816(c[mt][nt], ahi[mt], bh[hh * 2], bh[hh * 2 + 1]);
                        if (uselo)
                            mma16816(c[mt][nt], alo[mt], bh[hh * 2], bh[hh * 2 + 1]);
                    }
                }
            }
        }
    }

    // ---- epilogue ----
    #pragma unroll
    for (int mt = 0; mt < 2; mt++) {
        #pragma unroll
        for (int nt = 0; nt < 2 * NT2; nt++) {
            int rb = m0 + warp_m * 32 + mt * 16 + (lane >> 2);
            int nc = n0 + warp_n * (BN / 2) + nt * 8 + ((lane & 3) << 1);
            #pragma unroll
            for (int half = 0; half < 2; half++) {
                int m = rb + half * 8;
                if (m < M) {
                    #pragma unroll
                    for (int j = 0; j < 2; j++) {
                        int n = nc + j;
                        if (n < N) {
                            float v = c[mt][nt][half * 2 + j];
                            if (flags & F_BIAS)  v += bias[n];
                            if (flags & F_RESID) v += resid[(size_t)m * ldc + n];
                            if (flags & F_RELU)  v = fmaxf(v, 0.f);
                            if (flags & F_SPLIT) {
                                __half h, l;
                                split2h(v, h, l);
                                Ch[(size_t)m * ldc + n] = h;
                                if (Cl) Cl[(size_t)m * ldc + n] = l;
                            } else {
                                C[(size_t)m * ldc + n] = v;
                            }
                        }
                    }
                }
            }
        }
    }
}

#define HG_SMEM128 (2 * (2 * 128 * 128 + 64 * 128 * 2))   // 98304
#define HG_SMEM64  (2 * (2 * 128 * 64  + 32 * 64  * 2))   // 40960

// =====================================================================
// weight prep kernels
// =====================================================================
__global__ void repack_qkv_k(const float* __restrict__ Wq,
                             const float* __restrict__ Wk,
                             const float* __restrict__ Wv,
                             __half* __restrict__ d) {
    int i = blockIdx.x * blockDim.x + threadIdx.x;
    const int total = Lx * Dd * QKVW;
    if (i >= total) return;
    int j    = i % QKVW;
    int rest = i / QKVW;
    int dd   = rest % Dd;
    int l    = rest / Dd;
    int sel = j / HHd;
    int n   = j % HHd;
    int h  = n / HDd;
    int kk = n % HDd;
    const float* src = (sel == 0) ? Wq : (sel == 1) ? Wk : Wv;
    d[i] = __float2half_rn(src[((l * Hh + h) * Dd + dd) * HDd + kk]);
}

__global__ void tohalf2_k(const float* __restrict__ s1, __half2* __restrict__ d1,
                          int R1, int C1, int Cp21,
                          const float* __restrict__ s2, __half2* __restrict__ d2,
                          int R2, int C2, int Cp22) {
    int i = blockIdx.x * blockDim.x + threadIdx.x;
    int n1 = R1 * Cp21;
    if (i < n1) {
        int r = i / Cp21, c2 = (i - r * Cp21) << 1;
        const float* row = s1 + (size_t)r * C1;
        float v0 = (c2     < C1) ? row[c2]     : 0.f;
        float v1 = (c2 + 1 < C1) ? row[c2 + 1] : 0.f;
        d1[i] = __floats2half2_rn(v0, v1);
    } else {
        int j = i - n1;
        if (j >= R2 * Cp22) return;
        int r = j / Cp22, c2 = (j - r * Cp22) << 1;
        const float* row = s2 + (size_t)r * C2;
        float v0 = (c2     < C2) ? row[c2]     : 0.f;
        float v1 = (c2 + 1 < C2) ? row[c2 + 1] : 0.f;
        d2[j] = __floats2half2_rn(v0, v1);
    }
}

// ---- embedding ----
__global__ void embed_k(const int* __restrict__ idx,
                        const float* __restrict__ tok,
                        const float* __restrict__ pos) {
    int i = blockIdx.x * blockDim.x + threadIdx.x;
    if (i >= NT * Dd) return;
    int d = i % Dd;
    int n = i / Dd;
    int t = n % Tt;
    g_x[i] = tok[idx[n] * Dd + d] + pos[t * Dd + d];
}

// ---- layernorm -> hi/lo planes; warp-shuffle reduction (2 barriers) ----
__global__ void lnorm_split_k(const float* __restrict__ in,
                              __half* __restrict__ oh,
                              __half* __restrict__ ol,
                              const float* __restrict__ g, const float* __restrict__ b) {
    int row = blockIdx.x;
    const int tid = threadIdx.x, wid = tid >> 5, lane = tid & 31;
    const float* xr = in + (size_t)row * Dd;
    __shared__ float ws[8], ws2[8];
    __shared__ float s_mean, s_inv;

    float s = 0.f, ss = 0.f;
    for (int d = tid; d < Dd; d += 256) {
        float v = xr[d];
        s += v; ss += v * v;
    }
    #pragma unroll
    for (int o = 16; o; o >>= 1) {
        s  += __shfl_down_sync(0xFFFFFFFFu, s, o);
        ss += __shfl_down_sync(0xFFFFFFFFu, ss, o);
    }
    if (lane == 0) { ws[wid] = s; ws2[wid] = ss; }
    __syncthreads();
    if (wid == 0) {
        float a  = (lane < 8) ? ws[lane]  : 0.f;
        float a2 = (lane < 8) ? ws2[lane] : 0.f;
        #pragma unroll
        for (int o = 4; o; o >>= 1) {
            a  += __shfl_down_sync(0xFFFFFFFFu, a, o);
            a2 += __shfl_down_sync(0xFFFFFFFFu, a2, o);
        }
        if (lane == 0) {
            float mean = a / Dd;
            float var  = a2 / Dd - mean * mean;
            s_mean = mean;
            s_inv  = rsqrtf(var + 1e-5f);
        }
    }
    __syncthreads();
    const float mean = s_mean, inv = s_inv;
    for (int d = tid; d < PDd; d += 256) {
        float v = 0.f;
        if (d < Dd) v = (xr[d] - mean) * inv * g[d] + b[d];
        __half hi, lo;
        split2h(v, hi, lo);
        oh[(size_t)row * PDd + d] = hi;
        ol[(size_t)row * PDd + d] = lo;
    }
}

// =====================================================================
// attention (K,V staged in smem once per (b,h))
// =====================================================================
#define KSTR 47
#define VSTR 288
#define ATT_SMEM ((Tt*KSTR + HDd*VSTR + 8*48 + 8*46) * 4)

__global__ __launch_bounds__(256, 2) void attn_k(const float* __restrict__ qkv,
                                                 __half* __restrict__ oh,
                                                 __half* __restrict__ ol) {
    extern __shared__ float smf[];
    float* Ksm = smf;
    float* Vt  = Ksm + Tt * KSTR;
    float* qsm = Vt + HDd * VSTR;
    float* osm = qsm + 8 * 48;

    const int h = blockIdx.x, b = blockIdx.y;
    const int tid = threadIdx.x, w = tid >> 5, lane = tid & 31;
    const float* base = qkv + (size_t)(b * Tt) * QKVW + h * HDd;

    for (int idx = tid; idx < Tt * HDd; idx += 256) {
        int s = idx / HDd, d = idx - s * HDd;
        const float* row = base + (size_t)s * QKVW;
        Ksm[s * KSTR + d] = row[HHd + d];
        Vt [d * VSTR + s] = row[2 * HHd + d];
    }
    for (int idx = tid; idx < HDd * (VSTR - Tt); idx += 256) {
        int d = idx / (VSTR - Tt), s = Tt + idx % (VSTR - Tt);
        Vt[d * VSTR + s] = 0.f;
    }
    __syncthreads();

    const float scale = rsqrtf((float)HDd);
    for (int t = w; t < Tt; t += 8) {
        for (int d = lane; d < HDd; d += 32)
            qsm[w * 48 + d] = base[(size_t)t * QKVW + d];
        __syncwarp();

        const int ngrp = (t >> 5) + 1;
        float p[9];
        float m = -1e30f;
        for (int i = 0; i < ngrp; i++) {
            int s = lane + (i << 5);
            float acc = -1e30f;
            if (s <= t) {
                float a = 0.f;
                #pragma unroll
                for (int d = 0; d < HDd; d++)
                    a += qsm[w * 48 + d] * Ksm[s * KSTR + d];
                acc = a * scale;
            }
            p[i] = acc;
            m = fmaxf(m, acc);
        }
        #pragma unroll
        for (int o = 16; o; o >>= 1) m = fmaxf(m, __shfl_xor_sync(0xFFFFFFFFu, m, o));

        float sum = 0.f;
        for (int i = 0; i < ngrp; i++) {
            float e = __expf(p[i] - m);
            p[i] = e; sum += e;
        }
        #pragma unroll
        for (int o = 16; o; o >>= 1) sum += __shfl_xor_sync(0xFFFFFFFFu, sum, o);
        const float inv = 1.f / sum;

        for (int d = 0; d < HDd; d++) {
            float part = 0.f;
            for (int i = 0; i < ngrp; i++)
                part += p[i] * Vt[d * VSTR + lane + (i << 5)];
            #pragma unroll
            for (int o = 16; o; o >>= 1) part += __shfl_xor_sync(0xFFFFFFFFu, part, o);
            if (lane == 0) osm[w * 46 + d] = part * inv;
        }
        __syncwarp();

        for (int d = lane; d < HDd; d += 32) {
            float v = osm[w * 46 + d];
            __half hi, lo;
            split2h(v, hi, lo);
            oh[(size_t)(b * Tt + t) * HHd + h * HDd + d] = hi;
            ol[(size_t)(b * Tt + t) * HHd + h * HDd + d] = lo;
        }
        __syncwarp();
    }
}

// ---- host ----
template <typename T>
static T* sym_addr(const void* sym) {
    void* p = nullptr;
    cudaGetSymbolAddress(&p, sym);
    return (T*)p;
}

static void tgemm128(const __half* Ah, const __half* Al, const __half* Bh,
                     const float* bias, const float* resid,
                     float* C, __half* Ch, __half* Cl,
                     int M, int N, int K, int ApK, int BpN, int ldc, int flags) {
    dim3 g((M + 127) / 128, (N + 127) / 128);
    hgemm_k<128, 64><<<g, 256, HG_SMEM128>>>(Ah, Al, Bh, bias, resid, C, Ch, Cl,
                                             M, N, K, ApK, BpN, ldc, flags);
}
static void tgemm64(const __half* Ah, const __half* Al, const __half* Bh,
                    const float* bias, const float* resid,
                    float* C, __half* Ch, __half* Cl,
                    int M, int N, int K, int ApK, int BpN, int ldc, int flags) {
    dim3 g((M + 127) / 128, (N + 63) / 64);
    hgemm_k<64, 32><<<g, 256, HG_SMEM64>>>(Ah, Al, Bh, bias, resid, C, Ch, Cl,
                                           M, N, K, ApK, BpN, ldc, flags);
}

extern "C" void kernel_launch(void* const* d_in, const int* in_sizes, int n_in,
                              void* d_out, int out_size) {
    const int*   idx     = (const int*)  d_in[0];
    const float* tok_emb = (const float*)d_in[1];
    const float* pos_emb = (const float*)d_in[2];
    const float* Wq      = (const float*)d_in[3];
    const float* Wk      = (const float*)d_in[4];
    const float* Wv      = (const float*)d_in[5];
    const float* Wproj   = (const float*)d_in[6];
    const float* bproj   = (const float*)d_in[7];
    const float* ln1_g   = (const float*)d_in[8];
    const float* ln1_b   = (const float*)d_in[9];
    const float* ln2_g   = (const float*)d_in[10];
    const float* ln2_b   = (const float*)d_in[11];
    const float* W1      = (const float*)d_in[12];
    const float* b1      = (const float*)d_in[13];
    const float* W2      = (const float*)d_in[14];
    const float* b2      = (const float*)d_in[15];
    const float* lnf_g   = (const float*)d_in[16];
    const float* lnf_b   = (const float*)d_in[17];
    const float* Wlm     = (const float*)d_in[18];
    const float* blm     = (const float*)d_in[19];
    float* out = (float*)d_out;

    static bool attr_set = false;
    if (!attr_set) {
        cudaFuncSetAttribute((const void*)hgemm_k<128, 64>,
                             cudaFuncAttributeMaxDynamicSharedMemorySize, HG_SMEM128);
        cudaFuncSetAttribute((const void*)hgemm_k<64, 32>,
                             cudaFuncAttributeMaxDynamicSharedMemorySize, HG_SMEM64);
        cudaFuncSetAttribute(attn_k, cudaFuncAttributeMaxDynamicSharedMemorySize, ATT_SMEM);
        attr_set = true;
    }

    float* px   = sym_addr<float>(g_x);
    float* pqkv = sym_addr<float>(g_qkv);
    __half* phh  = sym_addr<__half>(g_hh);
    __half* phl  = sym_addr<__half>(g_hl);
    __half* poh  = sym_addr<__half>(g_oh);
    __half* pol  = sym_addr<__half>(g_ol);
    __half* pffh = sym_addr<__half>(g_ffh);
    __half* pwq  = sym_addr<__half>(g_wqkv);
    __half* pwp  = sym_addr<__half>(g_wp);
    __half* pw1  = sym_addr<__half>(g_w1);
    __half* pw2  = sym_addr<__half>(g_w2);
    __half* pwlm = sym_addr<__half>(g_wlm);

    // ---- weight prep + embed ----
    {
        int tot = Lx * Dd * QKVW;
        repack_qkv_k<<<(tot + 255) / 256, 256>>>(Wq, Wk, Wv, pwq);

        int nA = Lx * HHd * PDd / 2, nB = Lx * Dd * FFf / 2;
        tohalf2_k<<<(nA + nB + 255) / 256, 256>>>(
            Wproj, (__half2*)pwp, Lx * HHd, Dd, PDd / 2,
            W1,    (__half2*)pw1, Lx * Dd,  FFf, FFf / 2);

        int nC = Lx * FFf * PDd / 2, nD = Dd * PVv / 2;
        tohalf2_k<<<(nC + nD + 255) / 256, 256>>>(
            W2,  (__half2*)pw2,  Lx * FFf, Dd, PDd / 2,
            Wlm, (__half2*)pwlm, Dd,       Vv, PVv / 2);

        embed_k<<<(NT * Dd + 255) / 256, 256>>>(idx, tok_emb, pos_emb);
    }

    dim3 gATT(Hh, Bbt);

    for (int l = 0; l < Lx; l++) {
        lnorm_split_k<<<NT, 256>>>(px, phh, phl, ln1_g + l * Dd, ln1_b + l * Dd);
        tgemm128(phh, phl, pwq + (size_t)l * Dd * QKVW,
                 nullptr, nullptr, pqkv, nullptr, nullptr,
                 NT, QKVW, Dd, PDd, QKVW, QKVW, 0);
        attn_k<<<gATT, 256, ATT_SMEM>>>(pqkv, poh, pol);
        // proj: BN64/KCH32
        tgemm64(poh, pol, pwp + (size_t)l * HHd * PDd,
                bproj + l * Dd, px, px, nullptr, nullptr,
                NT, Dd, HHd, HHd, PDd, Dd, F_BIAS | F_RESID);
        lnorm_split_k<<<NT, 256>>>(px, phh, phl, ln2_g + l * Dd, ln2_b + l * Dd);
        // ff1: hi-only output (FF2 consumes single plane)
        tgemm128(phh, phl, pw1 + (size_t)l * Dd * FFf,
                 b1 + (size_t)l * FFf, nullptr, nullptr, pffh, nullptr,
                 NT, FFf, Dd, PDd, FFf, FFf, F_BIAS | F_RELU | F_SPLIT);
        // ff2: single-plane A (NOLO), BN64/KCH32
        tgemm64(pffh, nullptr, pw2 + (size_t)l * FFf * PDd,
                b2 + l * Dd, px, px, nullptr, nullptr,
                NT, Dd, FFf, FFf, PDd, Dd, F_BIAS | F_RESID | F_NOLO);
    }

    lnorm_split_k<<<NT, 256>>>(px, phh, phl, lnf_g, lnf_b);
    tgemm128(phh, phl, pwlm, blm, nullptr, out, nullptr, nullptr,
             NT, Vv, Dd, PDd, PVv, Vv, F_BIAS | F_NOLO);
}

// round 17
// speedup vs baseline: 1.3140x; 1.2416x over previous
#include <cuda_runtime.h>
#include <cuda_fp16.h>
#include <stdint.h>
#include <math.h>

// ---- problem constants ----
#define Lx   12
#define Dd   726
#define Hh   16
#define HDd  45
#define Tt   258
#define Vv   50257
#define Bbt  16
#define FFf  2904           // 4*D
#define NT   (Bbt*Tt)       // 4128 tokens
#define HHd  (Hh*HDd)       // 720
#define QKVW (3*HHd)        // 2160

#define PDd  728            // Dd padded to 8
#define PVv  50264          // Vv padded to 8

#define F_BIAS  1
#define F_RELU  2
#define F_RESID 4
#define F_HALF  8           // write __half output (hi plane)

// ---- fp32 scratch ----
__device__ float g_x   [NT*Dd];
__device__ float g_qkv [NT*QKVW];

// ---- fp16 planes (single plane everywhere) ----
__device__ __half g_hh [NT*PDd];      // LN output
__device__ __half g_oh [NT*HHd];      // attn output
__device__ __half g_ffh[NT*FFf];      // relu(ff1)
__device__ __half g_wqkv[Lx*Dd*QKVW];
__device__ __half g_wp  [Lx*HHd*PDd];
__device__ __half g_w1  [Lx*Dd*FFf];
__device__ __half g_w2  [Lx*FFf*PDd];
__device__ __half g_wlm [Dd*PVv];

// =====================================================================
// helpers
// =====================================================================
__device__ __forceinline__ uint32_t smem_u32(const void* p) {
    uint32_t a;
    asm("{ .reg .u64 t; cvta.to.shared.u64 t, %1; cvt.u32.u64 %0, t; }"
        : "=r"(a) : "l"(p));
    return a;
}
__device__ __forceinline__ void ldsm4(uint32_t& r0, uint32_t& r1,
                                      uint32_t& r2, uint32_t& r3, uint32_t addr) {
    asm volatile("ldmatrix.sync.aligned.m8n8.x4.shared.b16 {%0,%1,%2,%3}, [%4];"
                 : "=r"(r0), "=r"(r1), "=r"(r2), "=r"(r3) : "r"(addr));
}
__device__ __forceinline__ void ldsm4t(uint32_t& r0, uint32_t& r1,
                                       uint32_t& r2, uint32_t& r3, uint32_t addr) {
    asm volatile("ldmatrix.sync.aligned.m8n8.x4.trans.shared.b16 {%0,%1,%2,%3}, [%4];"
                 : "=r"(r0), "=r"(r1), "=r"(r2), "=r"(r3) : "r"(addr));
}
__device__ __forceinline__ void mma16816(float* c, const uint32_t* a,
                                         uint32_t b0, uint32_t b1) {
    asm volatile(
        "mma.sync.aligned.m16n8k16.row.col.f32.f16.f16.f32 "
        "{%0,%1,%2,%3},{%4,%5,%6,%7},{%8,%9},{%0,%1,%2,%3};"
        : "+f"(c[0]), "+f"(c[1]), "+f"(c[2]), "+f"(c[3])
        : "r"(a[0]), "r"(a[1]), "r"(a[2]), "r"(a[3]), "r"(b0), "r"(b1));
}
__device__ __forceinline__ void cpa16(uint32_t dst, const void* src, int bytes) {
    asm volatile("cp.async.cg.shared.global [%0], [%1], 16, %2;"
                 :: "r"(dst), "l"(src), "r"(bytes));
}
__device__ __forceinline__ void cpa_commit() {
    asm volatile("cp.async.commit_group;" ::: "memory");
}
__device__ __forceinline__ void cpa_wait0() {
    asm volatile("cp.async.wait_group 0;" ::: "memory");
}

// =====================================================================
// GEMM template: C[M,N] = A[M,K] @ B[K,N]; A,B single fp16 planes.
// <128,64>: CTA 128x128, stage 32KB (A16+B16), 2 CTA/SM.
// <64,32>:  CTA 128x64,  stage 12KB (A8+B4),  3 CTA/SM.
// 8 warps: 4m x 2n; warp tile 32 x (BN/2). One __syncthreads per chunk.
// =====================================================================
template<int BN, int KCHt>
__global__ __launch_bounds__(256, (BN == 128 ? 2 : 3)) void hgemm_k(
    const __half* __restrict__ Ah, const __half* __restrict__ Bh,
    const float* __restrict__ bias, const float* __restrict__ resid,
    float* __restrict__ C, __half* __restrict__ Ch,
    int M, int N, int K, int ApK, int BpN, int ldc, int flags)
{
    constexpr int NT2  = BN / 32;
    constexpr int KSN  = KCHt / 16;
    constexpr int ARB  = KCHt * 2;
    constexpr int BRB  = BN * 2;
    constexpr int ASEG = ARB / 16;
    constexpr int BSEG = BN / 8;
    constexpr uint32_t AMS  = (ARB == 128) ? 0x70u : 0x30u;
    constexpr uint32_t SB   = (uint32_t)(128 * ARB);           // B offset
    constexpr uint32_t STGT = SB + (uint32_t)(KCHt * BN * 2);  // stage bytes

    extern __shared__ __align__(1024) char smraw[];
    const uint32_t sbase = smem_u32(smraw);

    const int tid  = threadIdx.x;
    const int wid  = tid >> 5;
    const int lane = tid & 31;
    const int warp_m = wid & 3;
    const int warp_n = wid >> 2;

    const int m0 = blockIdx.x << 7;
    const int n0 = blockIdx.y * BN;
    const int nCh = (K + KCHt - 1) / KCHt;

    float c[2][2 * NT2][4];
    #pragma unroll
    for (int i = 0; i < 2; i++)
        #pragma unroll
        for (int j = 0; j < 2 * NT2; j++)
            #pragma unroll
            for (int q = 0; q < 4; q++) c[i][j][q] = 0.f;

    // A: unswizzled base + per-row mask; XOR applied AFTER the ks add.
    uint32_t abase[2], amask[2];
    #pragma unroll
    for (int mt = 0; mt < 2; mt++) {
        uint32_t o = (uint32_t)((warp_m * 32 + mt * 16 + (lane & 15)) * ARB
                                + ((lane >> 4) << 4));
        abase[mt] = o;
        amask[mt] = (o >> 3) & AMS;
    }
    // B fragment byte offsets; ks step (16*BRB) above swizzle bits -> additive.
    uint32_t boff[NT2];
    #pragma unroll
    for (int nt2 = 0; nt2 < NT2; nt2++) {
        uint32_t o = (uint32_t)((((lane >> 3) & 1) * 8 + (lane & 7)) * BRB
                                + warp_n * BN + nt2 * 32 + ((lane >> 4) << 4));
        if (BRB == 256) o ^= (o >> 4) & 0xF0u;
        else            o ^= (o >> 3) & 0x70u;
        boff[nt2] = o;
    }

    auto issue = [&](int ch) {
        const uint32_t st = sbase + (uint32_t)(ch & 1) * STGT;
        const int k0 = ch * KCHt;
        // A: 128 rows x ASEG segs of 16B
        #pragma unroll
        for (int i = 0; i < (128 * ASEG) / 256; i++) {
            int g = tid + (i << 8);
            int seg = g & (ASEG - 1), r = g / ASEG;
            int m = m0 + r, k = k0 + (seg << 3);
            int bytes = (m < M && k < ApK) ? 16 : 0;
            size_t gi = (size_t)m * ApK + k;
            uint32_t o = (uint32_t)(r * ARB + (seg << 4));
            o ^= (o >> 3) & AMS;
            cpa16(st + o, bytes ? (const void*)(Ah + gi) : (const void*)Ah, bytes);
        }
        // B: KCHt rows x BSEG segs of 16B
        #pragma unroll
        for (int i = 0; i < (KCHt * BSEG) / 256; i++) {
            int g = tid + (i << 8);
            int seg = g & (BSEG - 1), r = g / BSEG;
            int k = k0 + r, n = n0 + (seg << 3);
            int bytes = (k < K && n < BpN) ? 16 : 0;
            const void* p = bytes ? (const void*)(Bh + (size_t)k * BpN + n)
                                  : (const void*)Bh;
            uint32_t o = (uint32_t)(r * BRB + (seg << 4));
            if (BRB == 256) o ^= (o >> 4) & 0xF0u;
            else            o ^= (o >> 3) & 0x70u;
            cpa16(st + SB + o, p, bytes);
        }
    };

    issue(0);
    cpa_commit();

    for (int ch = 0; ch < nCh; ch++) {
        cpa_wait0();
        __syncthreads();

        if (ch + 1 < nCh) {
            issue(ch + 1);
            cpa_commit();
        }

        const uint32_t st = sbase + (uint32_t)(ch & 1) * STGT;
        #pragma unroll
        for (int ks = 0; ks < KSN; ks++) {
            uint32_t ahi[2][4];
            #pragma unroll
            for (int mt = 0; mt < 2; mt++) {
                uint32_t ad = st + ((abase[mt] + (uint32_t)(ks * 32)) ^ amask[mt]);
                ldsm4(ahi[mt][0], ahi[mt][1], ahi[mt][2], ahi[mt][3], ad);
            }
            #pragma unroll
            for (int nt2 = 0; nt2 < NT2; nt2++) {
                uint32_t bh[4];
                ldsm4t(bh[0], bh[1], bh[2], bh[3],
                       st + SB + boff[nt2] + (uint32_t)(ks * 16 * BRB));
                #pragma unroll
                for (int hh = 0; hh < 2; hh++) {
                    const int nt = nt2 * 2 + hh;
                    #pragma unroll
                    for (int mt = 0; mt < 2; mt++)
                        mma16816(c[mt][nt], ahi[mt], bh[hh * 2], bh[hh * 2 + 1]);
                }
            }
        }
    }

    // ---- epilogue ----
    #pragma unroll
    for (int mt = 0; mt < 2; mt++) {
        #pragma unroll
        for (int nt = 0; nt < 2 * NT2; nt++) {
            int rb = m0 + warp_m * 32 + mt * 16 + (lane >> 2);
            int nc = n0 + warp_n * (BN / 2) + nt * 8 + ((lane & 3) << 1);
            #pragma unroll
            for (int half = 0; half < 2; half++) {
                int m = rb + half * 8;
                if (m < M) {
                    #pragma unroll
                    for (int j = 0; j < 2; j++) {
                        int n = nc + j;
                        if (n < N) {
                            float v = c[mt][nt][half * 2 + j];
                            if (flags & F_BIAS)  v += bias[n];
                            if (flags & F_RESID) v += resid[(size_t)m * ldc + n];
                            if (flags & F_RELU)  v = fmaxf(v, 0.f);
                            if (flags & F_HALF)
                                Ch[(size_t)m * ldc + n] = __float2half_rn(v);
                            else
                                C[(size_t)m * ldc + n] = v;
                        }
                    }
                }
            }
        }
    }
}

#define HG_SMEM128 (2 * (128 * 128 + 64 * 128 * 2))   // 65536
#define HG_SMEM64  (2 * (128 * 64  + 32 * 64  * 2))   // 24576

// =====================================================================
// weight prep kernels
// =====================================================================
__global__ void repack_qkv_k(const float* __restrict__ Wq,
                             const float* __restrict__ Wk,
                             const float* __restrict__ Wv,
                             __half* __restrict__ d) {
    int i = blockIdx.x * blockDim.x + threadIdx.x;
    const int total = Lx * Dd * QKVW;
    if (i >= total) return;
    int j    = i % QKVW;
    int rest = i / QKVW;
    int dd   = rest % Dd;
    int l    = rest / Dd;
    int sel = j / HHd;
    int n   = j % HHd;
    int h  = n / HDd;
    int kk = n % HDd;
    const float* src = (sel == 0) ? Wq : (sel == 1) ? Wk : Wv;
    d[i] = __float2half_rn(src[((l * Hh + h) * Dd + dd) * HDd + kk]);
}

__global__ void tohalf2_k(const float* __restrict__ s1, __half2* __restrict__ d1,
                          int R1, int C1, int Cp21,
                          const float* __restrict__ s2, __half2* __restrict__ d2,
                          int R2, int C2, int Cp22) {
    int i = blockIdx.x * blockDim.x + threadIdx.x;
    int n1 = R1 * Cp21;
    if (i < n1) {
        int r = i / Cp21, c2 = (i - r * Cp21) << 1;
        const float* row = s1 + (size_t)r * C1;
        float v0 = (c2     < C1) ? row[c2]     : 0.f;
        float v1 = (c2 + 1 < C1) ? row[c2 + 1] : 0.f;
        d1[i] = __floats2half2_rn(v0, v1);
    } else {
        int j = i - n1;
        if (j >= R2 * Cp22) return;
        int r = j / Cp22, c2 = (j - r * Cp22) << 1;
        const float* row = s2 + (size_t)r * C2;
        float v0 = (c2     < C2) ? row[c2]     : 0.f;
        float v1 = (c2 + 1 < C2) ? row[c2 + 1] : 0.f;
        d2[j] = __floats2half2_rn(v0, v1);
    }
}

// ---- embedding ----
__global__ void embed_k(const int* __restrict__ idx,
                        const float* __restrict__ tok,
                        const float* __restrict__ pos) {
    int i = blockIdx.x * blockDim.x + threadIdx.x;
    if (i >= NT * Dd) return;
    int d = i % Dd;
    int n = i / Dd;
    int t = n % Tt;
    g_x[i] = tok[idx[n] * Dd + d] + pos[t * Dd + d];
}

// ---- layernorm -> single fp16 plane; shuffle reduction ----
__global__ void lnorm_h_k(const float* __restrict__ in,
                          __half* __restrict__ oh,
                          const float* __restrict__ g, const float* __restrict__ b) {
    int row = blockIdx.x;
    const int tid = threadIdx.x, wid = tid >> 5, lane = tid & 31;
    const float* xr = in + (size_t)row * Dd;
    __shared__ float ws[8], ws2[8];
    __shared__ float s_mean, s_inv;

    float s = 0.f, ss = 0.f;
    for (int d = tid; d < Dd; d += 256) {
        float v = xr[d];
        s += v; ss += v * v;
    }
    #pragma unroll
    for (int o = 16; o; o >>= 1) {
        s  += __shfl_down_sync(0xFFFFFFFFu, s, o);
        ss += __shfl_down_sync(0xFFFFFFFFu, ss, o);
    }
    if (lane == 0) { ws[wid] = s; ws2[wid] = ss; }
    __syncthreads();
    if (wid == 0) {
        float a  = (lane < 8) ? ws[lane]  : 0.f;
        float a2 = (lane < 8) ? ws2[lane] : 0.f;
        #pragma unroll
        for (int o = 4; o; o >>= 1) {
            a  += __shfl_down_sync(0xFFFFFFFFu, a, o);
            a2 += __shfl_down_sync(0xFFFFFFFFu, a2, o);
        }
        if (lane == 0) {
            float mean = a / Dd;
            float var  = a2 / Dd - mean * mean;
            s_mean = mean;
            s_inv  = rsqrtf(var + 1e-5f);
        }
    }
    __syncthreads();
    const float mean = s_mean, inv = s_inv;
    for (int d = tid; d < PDd; d += 256) {
        float v = 0.f;
        if (d < Dd) v = (xr[d] - mean) * inv * g[d] + b[d];
        oh[(size_t)row * PDd + d] = __float2half_rn(v);
    }
}

// =====================================================================
// attention (K,V staged in smem once per (b,h)); fp16 output plane
// =====================================================================
#define KSTR 47
#define VSTR 288
#define ATT_SMEM ((Tt*KSTR + HDd*VSTR + 8*48 + 8*46) * 4)

__global__ __launch_bounds__(256, 2) void attn_k(const float* __restrict__ qkv,
                                                 __half* __restrict__ oh) {
    extern __shared__ float smf[];
    float* Ksm = smf;
    float* Vt  = Ksm + Tt * KSTR;
    float* qsm = Vt + HDd * VSTR;
    float* osm = qsm + 8 * 48;

    const int h = blockIdx.x, b = blockIdx.y;
    const int tid = threadIdx.x, w = tid >> 5, lane = tid & 31;
    const float* base = qkv + (size_t)(b * Tt) * QKVW + h * HDd;

    for (int idx = tid; idx < Tt * HDd; idx += 256) {
        int s = idx / HDd, d = idx - s * HDd;
        const float* row = base + (size_t)s * QKVW;
        Ksm[s * KSTR + d] = row[HHd + d];
        Vt [d * VSTR + s] = row[2 * HHd + d];
    }
    for (int idx = tid; idx < HDd * (VSTR - Tt); idx += 256) {
        int d = idx / (VSTR - Tt), s = Tt + idx % (VSTR - Tt);
        Vt[d * VSTR + s] = 0.f;
    }
    __syncthreads();

    const float scale = rsqrtf((float)HDd);
    for (int t = w; t < Tt; t += 8) {
        for (int d = lane; d < HDd; d += 32)
            qsm[w * 48 + d] = base[(size_t)t * QKVW + d];
        __syncwarp();

        const int ngrp = (t >> 5) + 1;
        float p[9];
        float m = -1e30f;
        for (int i = 0; i < ngrp; i++) {
            int s = lane + (i << 5);
            float acc = -1e30f;
            if (s <= t) {
                float a = 0.f;
                #pragma unroll
                for (int d = 0; d < HDd; d++)
                    a += qsm[w * 48 + d] * Ksm[s * KSTR + d];
                acc = a * scale;
            }
            p[i] = acc;
            m = fmaxf(m, acc);
        }
        #pragma unroll
        for (int o = 16; o; o >>= 1) m = fmaxf(m, __shfl_xor_sync(0xFFFFFFFFu, m, o));

        float sum = 0.f;
        for (int i = 0; i < ngrp; i++) {
            float e = __expf(p[i] - m);
            p[i] = e; sum += e;
        }
        #pragma unroll
        for (int o = 16; o; o >>= 1) sum += __shfl_xor_sync(0xFFFFFFFFu, sum, o);
        const float inv = 1.f / sum;

        for (int d = 0; d < HDd; d++) {
            float part = 0.f;
            for (int i = 0; i < ngrp; i++)
                part += p[i] * Vt[d * VSTR + lane + (i << 5)];
            #pragma unroll
            for (int o = 16; o; o >>= 1) part += __shfl_xor_sync(0xFFFFFFFFu, part, o);
            if (lane == 0) osm[w * 46 + d] = part * inv;
        }
        __syncwarp();

        for (int d = lane; d < HDd; d += 32)
            oh[(size_t)(b * Tt + t) * HHd + h * HDd + d] =
                __float2half_rn(osm[w * 46 + d]);
        __syncwarp();
    }
}

// ---- host ----
template <typename T>
static T* sym_addr(const void* sym) {
    void* p = nullptr;
    cudaGetSymbolAddress(&p, sym);
    return (T*)p;
}

static void tgemm128(const __half* Ah, const __half* Bh,
                     const float* bias, const float* resid,
                     float* C, __half* Ch,
                     int M, int N, int K, int ApK, int BpN, int ldc, int flags) {
    dim3 g((M + 127) / 128, (N + 127) / 128);
    hgemm_k<128, 64><<<g, 256, HG_SMEM128>>>(Ah, Bh, bias, resid, C, Ch,
                                             M, N, K, ApK, BpN, ldc, flags);
}
static void tgemm64(const __half* Ah, const __half* Bh,
                    const float* bias, const float* resid,
                    float* C, __half* Ch,
                    int M, int N, int K, int ApK, int BpN, int ldc, int flags) {
    dim3 g((M + 127) / 128, (N + 63) / 64);
    hgemm_k<64, 32><<<g, 256, HG_SMEM64>>>(Ah, Bh, bias, resid, C, Ch,
                                           M, N, K, ApK, BpN, ldc, flags);
}

extern "C" void kernel_launch(void* const* d_in, const int* in_sizes, int n_in,
                              void* d_out, int out_size) {
    const int*   idx     = (const int*)  d_in[0];
    const float* tok_emb = (const float*)d_in[1];
    const float* pos_emb = (const float*)d_in[2];
    const float* Wq      = (const float*)d_in[3];
    const float* Wk      = (const float*)d_in[4];
    const float* Wv      = (const float*)d_in[5];
    const float* Wproj   = (const float*)d_in[6];
    const float* bproj   = (const float*)d_in[7];
    const float* ln1_g   = (const float*)d_in[8];
    const float* ln1_b   = (const float*)d_in[9];
    const float* ln2_g   = (const float*)d_in[10];
    const float* ln2_b   = (const float*)d_in[11];
    const float* W1      = (const float*)d_in[12];
    const float* b1      = (const float*)d_in[13];
    const float* W2      = (const float*)d_in[14];
    const float* b2      = (const float*)d_in[15];
    const float* lnf_g   = (const float*)d_in[16];
    const float* lnf_b   = (const float*)d_in[17];
    const float* Wlm     = (const float*)d_in[18];
    const float* blm     = (const float*)d_in[19];
    float* out = (float*)d_out;

    static bool attr_set = false;
    if (!attr_set) {
        cudaFuncSetAttribute((const void*)hgemm_k<128, 64>,
                             cudaFuncAttributeMaxDynamicSharedMemorySize, HG_SMEM128);
        cudaFuncSetAttribute((const void*)hgemm_k<64, 32>,
                             cudaFuncAttributeMaxDynamicSharedMemorySize, HG_SMEM64);
        cudaFuncSetAttribute(attn_k, cudaFuncAttributeMaxDynamicSharedMemorySize, ATT_SMEM);
        attr_set = true;
    }

    float* px   = sym_addr<float>(g_x);
    float* pqkv = sym_addr<float>(g_qkv);
    __half* phh  = sym_addr<__half>(g_hh);
    __half* poh  = sym_addr<__half>(g_oh);
    __half* pffh = sym_addr<__half>(g_ffh);
    __half* pwq  = sym_addr<__half>(g_wqkv);
    __half* pwp  = sym_addr<__half>(g_wp);
    __half* pw1  = sym_addr<__half>(g_w1);
    __half* pw2  = sym_addr<__half>(g_w2);
    __half* pwlm = sym_addr<__half>(g_wlm);

    // ---- weight prep + embed ----
    {
        int tot = Lx * Dd * QKVW;
        repack_qkv_k<<<(tot + 255) / 256, 256>>>(Wq, Wk, Wv, pwq);

        int nA = Lx * HHd * PDd / 2, nB = Lx * Dd * FFf / 2;
        tohalf2_k<<<(nA + nB + 255) / 256, 256>>>(
            Wproj, (__half2*)pwp, Lx * HHd, Dd, PDd / 2,
            W1,    (__half2*)pw1, Lx * Dd,  FFf, FFf / 2);

        int nC = Lx * FFf * PDd / 2, nD = Dd * PVv / 2;
        tohalf2_k<<<(nC + nD + 255) / 256, 256>>>(
            W2,  (__half2*)pw2,  Lx * FFf, Dd, PDd / 2,
            Wlm, (__half2*)pwlm, Dd,       Vv, PVv / 2);

        embed_k<<<(NT * Dd + 255) / 256, 256>>>(idx, tok_emb, pos_emb);
    }

    dim3 gATT(Hh, Bbt);

    for (int l = 0; l < Lx; l++) {
        lnorm_h_k<<<NT, 256>>>(px, phh, ln1_g + l * Dd, ln1_b + l * Dd);
        // qkv = h @ Wqkv
        tgemm128(phh, pwq + (size_t)l * Dd * QKVW,
                 nullptr, nullptr, pqkv, nullptr,
                 NT, QKVW, Dd, PDd, QKVW, QKVW, 0);
        attn_k<<<gATT, 256, ATT_SMEM>>>(pqkv, poh);
        // proj
        tgemm64(poh, pwp + (size_t)l * HHd * PDd,
                bproj + l * Dd, px, px, nullptr,
                NT, Dd, HHd, HHd, PDd, Dd, F_BIAS | F_RESID);
        lnorm_h_k<<<NT, 256>>>(px, phh, ln2_g + l * Dd, ln2_b + l * Dd);
        // ff1 (fp16 output)
        tgemm128(phh, pw1 + (size_t)l * Dd * FFf,
                 b1 + (size_t)l * FFf, nullptr, nullptr, pffh,
                 NT, FFf, Dd, PDd, FFf, FFf, F_BIAS | F_RELU | F_HALF);
        // ff2
        tgemm64(pffh, pw2 + (size_t)l * FFf * PDd,
                b2 + l * Dd, px, px, nullptr,
                NT, Dd, FFf, FFf, PDd, Dd, F_BIAS | F_RESID);
    }

    lnorm_h_k<<<NT, 256>>>(px, phh, lnf_g, lnf_b);
    tgemm128(phh, pwlm, blm, nullptr, out, nullptr,
             NT, Vv, Dd, PDd, PVv, Vv, F_BIAS);
}